// round 3
// baseline (speedup 1.0000x reference)
#include <cuda_runtime.h>
#include <math.h>

#define N_NODES 50000
#define N_EDGES 800000
#define FEAT 256
#define HID 256
#define OUT 40
#define N_BATCH 10000

// ---------------- scratch (device globals; no allocation allowed) ----------------
__device__ float g_h1[N_NODES * HID];     // h1, later x1 (post BN+relu)
__device__ float g_num1[N_NODES * HID];
__device__ float g_den1[N_NODES];
__device__ float g_h2[N_NODES * OUT];     // h2, later x2 (= num2/den2)
__device__ float g_num2[N_NODES * OUT];
__device__ float g_den2[N_NODES];
__device__ float g_sum1[HID], g_sq1[HID], g_scale1[HID], g_shift1[HID];
__device__ float g_sum2[OUT], g_sq2[OUT], g_scale2[OUT], g_shift2[OUT];
__device__ int   g_is64;

// ---------------- dtype detection for edge_index / batch_nodes -------------------
// int32 data read as int64 combines two ids: v = lo + hi*2^32, hi is a node id
// (nonzero w.p. 1-1/50000 per sample) -> out of [0, N_NODES). 64 samples => certain.
__global__ void detect_kernel(const void* ei) {
    if (threadIdx.x == 0) {
        const long long* p = (const long long*)ei;
        int ok64 = 1;
        for (int i = 0; i < 64; i++) {
            long long v = p[i];
            if (v < 0 || v >= (long long)N_NODES) { ok64 = 0; break; }
        }
        g_is64 = ok64;
    }
}

__device__ __forceinline__ int load_idx(const void* p, long i) {
    return g_is64 ? (int)((const long long*)p)[i] : ((const int*)p)[i];
}

// ---------------- zero accumulators (every launch; graph-safe) -------------------
__global__ void zero_kernel() {
    long i = (long)blockIdx.x * 256 + threadIdx.x;
    if (i < (long)N_NODES * HID) g_num1[i] = 0.f;
    if (i < (long)N_NODES * OUT) g_num2[i] = 0.f;
    if (i < N_NODES) { g_den1[i] = 0.f; g_den2[i] = 0.f; }
    if (i < HID) { g_sum1[i] = 0.f; g_sq1[i] = 0.f; }
    if (i < OUT) { g_sum2[i] = 0.f; g_sq2[i] = 0.f; }
}

// ---------------- GEMM1: h1[N,256] = features[N,256] @ W1[256,256] + b1 ----------
__global__ __launch_bounds__(256) void gemm1_kernel(
    const float* __restrict__ A, const float* __restrict__ W,
    const float* __restrict__ bias)
{
    __shared__ float As[16][68];   // [k][row], padded
    __shared__ float Bs[16][68];   // [k][col], padded
    const int tid = threadIdx.x;
    const int bm = blockIdx.x * 64;
    const int bn = blockIdx.y * 64;
    const int ty = tid >> 4, tx = tid & 15;

    const int lr = tid >> 2;          // A-load row 0..63
    const int lk = (tid & 3) * 4;     // A-load k offset
    const int wr = tid >> 4;          // W-load k row 0..15
    const int wc = (tid & 15) * 4;    // W-load col

    float acc[4][4] = {};

    for (int k0 = 0; k0 < FEAT; k0 += 16) {
        float4 av = make_float4(0.f, 0.f, 0.f, 0.f);
        int gr = bm + lr;
        if (gr < N_NODES)
            av = *(const float4*)(A + (long)gr * FEAT + k0 + lk);
        As[lk + 0][lr] = av.x; As[lk + 1][lr] = av.y;
        As[lk + 2][lr] = av.z; As[lk + 3][lr] = av.w;

        *(float4*)&Bs[wr][wc] = *(const float4*)(W + (long)(k0 + wr) * HID + bn + wc);
        __syncthreads();

        #pragma unroll
        for (int k = 0; k < 16; k++) {
            float a[4], b[4];
            #pragma unroll
            for (int i = 0; i < 4; i++) a[i] = As[k][ty * 4 + i];
            #pragma unroll
            for (int j = 0; j < 4; j++) b[j] = Bs[k][tx * 4 + j];
            #pragma unroll
            for (int i = 0; i < 4; i++)
                #pragma unroll
                for (int j = 0; j < 4; j++)
                    acc[i][j] = fmaf(a[i], b[j], acc[i][j]);
        }
        __syncthreads();
    }

    #pragma unroll
    for (int i = 0; i < 4; i++) {
        int r = bm + ty * 4 + i;
        if (r < N_NODES) {
            #pragma unroll
            for (int j = 0; j < 4; j++) {
                int c = bn + tx * 4 + j;
                g_h1[(long)r * HID + c] = acc[i][j] + bias[c];
            }
        }
    }
}

// ---------------- Edge pass 1: gaussian kernel + weighted scatter (C=256) --------
__global__ __launch_bounds__(256) void edge1_kernel(
    const void* __restrict__ ei, const float* __restrict__ gamma)
{
    int warp = (blockIdx.x * 256 + threadIdx.x) >> 5;
    int lane = threadIdx.x & 31;
    if (warp >= N_EDGES) return;
    int src = load_idx(ei, warp);
    int dst = load_idx(ei, (long)N_EDGES + warp);

    const float4* hs = (const float4*)(g_h1 + (long)src * HID);
    const float4* hd = (const float4*)(g_h1 + (long)dst * HID);
    float4 a0 = hs[lane], a1 = hs[lane + 32];
    float4 b0 = hd[lane], b1 = hd[lane + 32];

    float dx = a0.x - b0.x, dy = a0.y - b0.y, dz = a0.z - b0.z, dw = a0.w - b0.w;
    float d2 = dx*dx + dy*dy + dz*dz + dw*dw;
    dx = a1.x - b1.x; dy = a1.y - b1.y; dz = a1.z - b1.z; dw = a1.w - b1.w;
    d2 += dx*dx + dy*dy + dz*dz + dw*dw;
    #pragma unroll
    for (int o = 16; o > 0; o >>= 1) d2 += __shfl_xor_sync(0xffffffffu, d2, o);

    float w = expf(-gamma[0] * d2);

    float* np = g_num1 + (long)dst * HID;
    asm volatile("red.global.add.v4.f32 [%0], {%1,%2,%3,%4};"
                 :: "l"(np + 4 * lane),
                    "f"(w * a0.x), "f"(w * a0.y), "f"(w * a0.z), "f"(w * a0.w)
                 : "memory");
    asm volatile("red.global.add.v4.f32 [%0], {%1,%2,%3,%4};"
                 :: "l"(np + 128 + 4 * lane),
                    "f"(w * a1.x), "f"(w * a1.y), "f"(w * a1.z), "f"(w * a1.w)
                 : "memory");
    if (lane == 0) atomicAdd(g_den1 + dst, w);
}

// ---------------- x1 = num1/den1, accumulate BN1 stats; x1 -> g_h1 ---------------
__global__ __launch_bounds__(256) void finalize1_kernel() {
    int c = threadIdx.x;                  // channel 0..255
    int r0 = blockIdx.x * 128;
    int r1 = min(r0 + 128, N_NODES);
    float s = 0.f, ss = 0.f;
    for (int r = r0; r < r1; r++) {
        float den = g_den1[r] + 1e-16f;
        float v = g_num1[(long)r * HID + c] / den;
        g_h1[(long)r * HID + c] = v;
        s += v; ss += v * v;
    }
    atomicAdd(g_sum1 + c, s);
    atomicAdd(g_sq1 + c, ss);
}

__global__ void bnprep1_kernel(const float* __restrict__ w, const float* __restrict__ b) {
    int c = threadIdx.x;
    float mean = g_sum1[c] * (1.f / N_NODES);
    float var  = g_sq1[c] * (1.f / N_NODES) - mean * mean;
    float sc = w[c] * rsqrtf(var + 1e-5f);
    g_scale1[c] = sc;
    g_shift1[c] = b[c] - mean * sc;
}

__global__ __launch_bounds__(256) void bnapply1_kernel() {
    long i = (long)blockIdx.x * 256 + threadIdx.x;       // float4 index
    if (i >= (long)N_NODES * HID / 4) return;
    float4 x = ((const float4*)g_h1)[i];
    int c4 = (int)(i & 63);
    float4 sc = ((const float4*)g_scale1)[c4];
    float4 sh = ((const float4*)g_shift1)[c4];
    x.x = fmaxf(fmaf(x.x, sc.x, sh.x), 0.f);
    x.y = fmaxf(fmaf(x.y, sc.y, sh.y), 0.f);
    x.z = fmaxf(fmaf(x.z, sc.z, sh.z), 0.f);
    x.w = fmaxf(fmaf(x.w, sc.w, sh.w), 0.f);
    ((float4*)g_h1)[i] = x;
}

// ---------------- GEMM2: h2[N,40] = x1[N,256] @ W2[256,40] + b2 ------------------
__global__ __launch_bounds__(256) void gemm2_kernel(
    const float* __restrict__ W2, const float* __restrict__ b2)
{
    __shared__ float As[32][68];   // [k][row], padded
    __shared__ float Bs[32][40];
    const int tid = threadIdx.x;
    const int bm = blockIdx.x * 64;
    const int row = tid >> 2;           // 0..63
    const int cg = (tid & 3) * 10;      // column group

    float acc[10] = {};

    for (int k0 = 0; k0 < HID; k0 += 32) {
        #pragma unroll
        for (int t = 0; t < 2; t++) {
            int li = tid + t * 256;          // float4 index 0..511
            int r = li >> 3;                 // row 0..63
            int kk = (li & 7) * 4;           // k offset
            float4 v = make_float4(0.f, 0.f, 0.f, 0.f);
            int gr = bm + r;
            if (gr < N_NODES)
                v = *(const float4*)(g_h1 + (long)gr * HID + k0 + kk);
            As[kk + 0][r] = v.x; As[kk + 1][r] = v.y;
            As[kk + 2][r] = v.z; As[kk + 3][r] = v.w;
        }
        for (int i = tid; i < 32 * 40; i += 256)
            Bs[i / 40][i % 40] = W2[(long)(k0 + i / 40) * OUT + (i % 40)];
        __syncthreads();

        #pragma unroll
        for (int k = 0; k < 32; k++) {
            float a = As[k][row];
            #pragma unroll
            for (int j = 0; j < 10; j++)
                acc[j] = fmaf(a, Bs[k][cg + j], acc[j]);
        }
        __syncthreads();
    }

    int gr = bm + row;
    if (gr < N_NODES) {
        #pragma unroll
        for (int j = 0; j < 10; j++)
            g_h2[(long)gr * OUT + cg + j] = acc[j] + b2[cg + j];
    }
}

// ---------------- Edge pass 2 (C=40) ---------------------------------------------
__global__ __launch_bounds__(256) void edge2_kernel(
    const void* __restrict__ ei, const float* __restrict__ gamma)
{
    int warp = (blockIdx.x * 256 + threadIdx.x) >> 5;
    int lane = threadIdx.x & 31;
    if (warp >= N_EDGES) return;
    int src = load_idx(ei, warp);
    int dst = load_idx(ei, (long)N_EDGES + warp);

    const float2* hs = (const float2*)(g_h2 + (long)src * OUT);
    const float2* hd = (const float2*)(g_h2 + (long)dst * OUT);
    float2 a = make_float2(0.f, 0.f);
    float d2 = 0.f;
    if (lane < 20) {
        a = hs[lane];
        float2 b = hd[lane];
        float dx = a.x - b.x, dy = a.y - b.y;
        d2 = dx * dx + dy * dy;
    }
    #pragma unroll
    for (int o = 16; o > 0; o >>= 1) d2 += __shfl_xor_sync(0xffffffffu, d2, o);

    float w = expf(-gamma[0] * d2);

    if (lane < 20) {
        float* np = g_num2 + (long)dst * OUT + 2 * lane;
        asm volatile("red.global.add.v2.f32 [%0], {%1,%2};"
                     :: "l"(np), "f"(w * a.x), "f"(w * a.y) : "memory");
    }
    if (lane == 0) atomicAdd(g_den2 + dst, w);
}

// ---------------- x2 = num2/den2, BN2 stats; x2 -> g_h2 --------------------------
__global__ __launch_bounds__(320) void finalize2_kernel() {
    int c = threadIdx.x % 40;
    int rg = threadIdx.x / 40;    // 0..7
    int r0 = blockIdx.x * 128;
    int r1 = min(r0 + 128, N_NODES);
    float s = 0.f, ss = 0.f;
    for (int r = r0 + rg; r < r1; r += 8) {
        float den = g_den2[r] + 1e-16f;
        float v = g_num2[(long)r * OUT + c] / den;
        g_h2[(long)r * OUT + c] = v;
        s += v; ss += v * v;
    }
    atomicAdd(g_sum2 + c, s);
    atomicAdd(g_sq2 + c, ss);
}

__global__ void bnprep2_kernel(const float* __restrict__ w, const float* __restrict__ b) {
    int c = threadIdx.x;
    float mean = g_sum2[c] * (1.f / N_NODES);
    float var  = g_sq2[c] * (1.f / N_NODES) - mean * mean;
    float sc = w[c] * rsqrtf(var + 1e-5f);
    g_scale2[c] = sc;
    g_shift2[c] = b[c] - mean * sc;
}

// ---------------- gather batch nodes, BN2 + relu + log_softmax -------------------
__global__ __launch_bounds__(256) void final_kernel(
    const void* __restrict__ bnodes, float* __restrict__ out)
{
    int warp = (blockIdx.x * 256 + threadIdx.x) >> 5;
    int lane = threadIdx.x & 31;
    if (warp >= N_BATCH) return;
    int node = load_idx(bnodes, warp);
    const float* x = g_h2 + (long)node * OUT;

    float v0 = fmaxf(fmaf(x[lane], g_scale2[lane], g_shift2[lane]), 0.f);
    float v1 = -1e30f;
    if (lane < 8)
        v1 = fmaxf(fmaf(x[32 + lane], g_scale2[32 + lane], g_shift2[32 + lane]), 0.f);

    float m = fmaxf(v0, v1);
    #pragma unroll
    for (int o = 16; o > 0; o >>= 1) m = fmaxf(m, __shfl_xor_sync(0xffffffffu, m, o));
    float e = expf(v0 - m) + (lane < 8 ? expf(v1 - m) : 0.f);
    #pragma unroll
    for (int o = 16; o > 0; o >>= 1) e += __shfl_xor_sync(0xffffffffu, e, o);
    float lz = m + logf(e);

    out[(long)warp * OUT + lane] = v0 - lz;
    if (lane < 8) out[(long)warp * OUT + 32 + lane] = v1 - lz;
}

// ---------------- launcher --------------------------------------------------------
extern "C" void kernel_launch(void* const* d_in, const int* in_sizes, int n_in,
                              void* d_out, int out_size) {
    const float* features = (const float*)d_in[0];
    const void*  edge     = d_in[1];
    const void*  batch    = d_in[2];
    const float* W1 = (const float*)d_in[3];
    const float* b1 = (const float*)d_in[4];
    const float* g1 = (const float*)d_in[5];
    const float* W2 = (const float*)d_in[6];
    const float* b2 = (const float*)d_in[7];
    const float* g2 = (const float*)d_in[8];
    const float* bn1w = (const float*)d_in[9];
    const float* bn1b = (const float*)d_in[10];
    const float* bn2w = (const float*)d_in[11];
    const float* bn2b = (const float*)d_in[12];
    float* out = (float*)d_out;

    detect_kernel<<<1, 64>>>(edge);
    zero_kernel<<<(N_NODES * HID + 255) / 256, 256>>>();

    dim3 gg1((N_NODES + 63) / 64, HID / 64);
    gemm1_kernel<<<gg1, 256>>>(features, W1, b1);

    edge1_kernel<<<(N_EDGES * 32 + 255) / 256, 256>>>(edge, g1);
    finalize1_kernel<<<(N_NODES + 127) / 128, 256>>>();
    bnprep1_kernel<<<1, HID>>>(bn1w, bn1b);
    bnapply1_kernel<<<(N_NODES * HID / 4 + 255) / 256, 256>>>();

    gemm2_kernel<<<(N_NODES + 63) / 64, 256>>>(W2, b2);

    edge2_kernel<<<(N_EDGES * 32 + 255) / 256, 256>>>(edge, g2);
    finalize2_kernel<<<(N_NODES + 127) / 128, 320>>>();
    bnprep2_kernel<<<1, OUT>>>(bn2w, bn2b);

    final_kernel<<<(N_BATCH * 32 + 255) / 256, 256>>>(batch, out);
}

// round 4
// speedup vs baseline: 1.1970x; 1.1970x over previous
#include <cuda_runtime.h>
#include <math.h>

#define N_NODES 50000
#define N_EDGES 800000
#define FEAT 256
#define HID 256
#define OUT 40
#define N_BATCH 10000

// ---------------- scratch (device globals; no allocation allowed) ----------------
__device__ float g_h1[N_NODES * HID];     // h1 (gemm1 out)
__device__ float g_x1[N_NODES * HID];     // x1 = num1/den1 (pre-BN)
__device__ float g_h2[N_NODES * OUT];     // h2 (gemm2 out)
__device__ float g_x2[N_NODES * OUT];     // x2 = num2/den2 (pre-BN)
__device__ float g_sum1[HID], g_sq1[HID], g_scale1[HID], g_shift1[HID];
__device__ float g_sum2[OUT], g_sq2[OUT], g_scale2[OUT], g_shift2[OUT];
__device__ int   g_is64;

// CSR (built per launch; graph-capturable, deterministic up to fp-sum order)
__device__ int g_cnt[N_NODES];        // in-degree histogram
__device__ int g_off[N_NODES];        // row starts (exclusive scan)
__device__ int g_cur[N_NODES];        // scatter cursors
__device__ int g_csr_src[N_EDGES];    // src ids grouped by dst

// ---------------- dtype detection for edge_index / batch_nodes -------------------
__global__ void detect_kernel(const void* ei) {
    if (threadIdx.x == 0) {
        const long long* p = (const long long*)ei;
        int ok64 = 1;
        for (int i = 0; i < 64; i++) {
            long long v = p[i];
            if (v < 0 || v >= (long long)N_NODES) { ok64 = 0; break; }
        }
        g_is64 = ok64;
    }
}

__device__ __forceinline__ int load_idx(const void* p, long i) {
    return g_is64 ? (int)((const long long*)p)[i] : ((const int*)p)[i];
}

// ---------------- zero small accumulators (every launch) -------------------------
__global__ void zero_kernel() {
    int i = blockIdx.x * 256 + threadIdx.x;
    if (i < N_NODES) g_cnt[i] = 0;
    if (i < HID) { g_sum1[i] = 0.f; g_sq1[i] = 0.f; }
    if (i < OUT) { g_sum2[i] = 0.f; g_sq2[i] = 0.f; }
}

// ---------------- CSR build ------------------------------------------------------
__global__ void hist_kernel(const void* __restrict__ ei) {
    int i = blockIdx.x * 256 + threadIdx.x;
    if (i >= N_EDGES) return;
    int dst = load_idx(ei, (long)N_EDGES + i);
    atomicAdd(&g_cnt[dst], 1);
}

__global__ void scan_kernel() {
    __shared__ int part[1024];
    const int t = threadIdx.x;
    const int CH = (N_NODES + 1023) / 1024;   // 49
    int beg = t * CH, end = min(beg + CH, N_NODES);
    int s = 0;
    for (int i = beg; i < end; i++) s += g_cnt[i];
    part[t] = s;
    __syncthreads();
    for (int o = 1; o < 1024; o <<= 1) {
        int v = (t >= o) ? part[t - o] : 0;
        __syncthreads();
        part[t] += v;
        __syncthreads();
    }
    int base = (t == 0) ? 0 : part[t - 1];
    for (int i = beg; i < end; i++) {
        g_off[i] = base;
        g_cur[i] = base;
        base += g_cnt[i];
    }
}

__global__ void scatter_kernel(const void* __restrict__ ei) {
    int i = blockIdx.x * 256 + threadIdx.x;
    if (i >= N_EDGES) return;
    int src = load_idx(ei, i);
    int dst = load_idx(ei, (long)N_EDGES + i);
    int pos = atomicAdd(&g_cur[dst], 1);
    g_csr_src[pos] = src;
}

// ---------------- GEMM1: h1[N,256] = features @ W1 + b1 (128x128, dbuf, 8x8) -----
__global__ __launch_bounds__(256) void gemm1_kernel(
    const float* __restrict__ A, const float* __restrict__ W,
    const float* __restrict__ bias)
{
    __shared__ float As[2][8][128];
    __shared__ float Bs[2][8][128];
    const int tid = threadIdx.x;
    const int bm = blockIdx.x * 128;
    const int bn = blockIdx.y * 128;
    const int tx = tid & 15;
    const int ty = tid >> 4;

    const int arow = tid >> 1;             // 0..127
    const int acol = (tid & 1) * 4;        // 0 or 4
    const int brow = tid >> 5;             // 0..7
    const int bcol = (tid & 31) * 4;       // 0..124

    const float* Aptr = A + (long)min(bm + arow, N_NODES - 1) * FEAT + acol;
    const float* Wptr = W + (long)brow * HID + bn + bcol;

    float acc[2][2][4][4];
    #pragma unroll
    for (int p = 0; p < 2; p++)
        #pragma unroll
        for (int q = 0; q < 2; q++)
            #pragma unroll
            for (int i = 0; i < 4; i++)
                #pragma unroll
                for (int j = 0; j < 4; j++) acc[p][q][i][j] = 0.f;

    // preload tile 0
    {
        float4 av = *(const float4*)Aptr;
        float4 bv = *(const float4*)Wptr;
        As[0][acol + 0][arow] = av.x; As[0][acol + 1][arow] = av.y;
        As[0][acol + 2][arow] = av.z; As[0][acol + 3][arow] = av.w;
        *(float4*)&Bs[0][brow][bcol] = bv;
    }
    __syncthreads();

    int buf = 0;
    #pragma unroll 1
    for (int kt = 0; kt < FEAT / 8; kt++) {
        float4 na, nb;
        const bool has_next = (kt + 1 < FEAT / 8);
        if (has_next) {
            na = *(const float4*)(Aptr + (kt + 1) * 8);
            nb = *(const float4*)(Wptr + (long)(kt + 1) * 8 * HID);
        }
        #pragma unroll
        for (int k = 0; k < 8; k++) {
            float4 a0 = *(const float4*)&As[buf][k][ty * 4];
            float4 a1 = *(const float4*)&As[buf][k][64 + ty * 4];
            float4 b0 = *(const float4*)&Bs[buf][k][tx * 4];
            float4 b1 = *(const float4*)&Bs[buf][k][64 + tx * 4];
            float am[2][4] = {{a0.x, a0.y, a0.z, a0.w}, {a1.x, a1.y, a1.z, a1.w}};
            float bv[2][4] = {{b0.x, b0.y, b0.z, b0.w}, {b1.x, b1.y, b1.z, b1.w}};
            #pragma unroll
            for (int p = 0; p < 2; p++)
                #pragma unroll
                for (int q = 0; q < 2; q++)
                    #pragma unroll
                    for (int i = 0; i < 4; i++)
                        #pragma unroll
                        for (int j = 0; j < 4; j++)
                            acc[p][q][i][j] = fmaf(am[p][i], bv[q][j], acc[p][q][i][j]);
        }
        if (has_next) {
            int nbuf = buf ^ 1;
            As[nbuf][acol + 0][arow] = na.x; As[nbuf][acol + 1][arow] = na.y;
            As[nbuf][acol + 2][arow] = na.z; As[nbuf][acol + 3][arow] = na.w;
            *(float4*)&Bs[nbuf][brow][bcol] = nb;
        }
        __syncthreads();
        buf ^= 1;
    }

    float4 bias4[2];
    bias4[0] = *(const float4*)(bias + bn + tx * 4);
    bias4[1] = *(const float4*)(bias + bn + 64 + tx * 4);
    #pragma unroll
    for (int p = 0; p < 2; p++) {
        #pragma unroll
        for (int i = 0; i < 4; i++) {
            int r = bm + p * 64 + ty * 4 + i;
            if (r < N_NODES) {
                #pragma unroll
                for (int q = 0; q < 2; q++) {
                    int c = bn + q * 64 + tx * 4;
                    float4 o;
                    o.x = acc[p][q][i][0] + bias4[q].x;
                    o.y = acc[p][q][i][1] + bias4[q].y;
                    o.z = acc[p][q][i][2] + bias4[q].z;
                    o.w = acc[p][q][i][3] + bias4[q].w;
                    *(float4*)&g_h1[(long)r * HID + c] = o;
                }
            }
        }
    }
}

// ---------------- Layer-1 aggregation: CSR, warp-per-node, fused finalize+stats --
__global__ __launch_bounds__(256) void agg1_kernel(const float* __restrict__ gamma) {
    const int lane = threadIdx.x & 31;
    const int gwarp = (blockIdx.x * 256 + threadIdx.x) >> 5;
    const int nwarps = gridDim.x * 8;
    const float gam = gamma[0];

    // per-lane channel partials: channels [4*lane..4*lane+3] and [128+4*lane..+3]
    float ps0[4] = {0, 0, 0, 0}, ps1[4] = {0, 0, 0, 0};
    float pq0[4] = {0, 0, 0, 0}, pq1[4] = {0, 0, 0, 0};

    for (int node = gwarp; node < N_NODES; node += nwarps) {
        const float4* hd = (const float4*)(g_h1 + (long)node * HID);
        float4 d0 = hd[lane], d1 = hd[lane + 32];
        float4 a0 = make_float4(0.f, 0.f, 0.f, 0.f);
        float4 a1 = make_float4(0.f, 0.f, 0.f, 0.f);
        float den = 0.f;
        const int beg = g_off[node];
        const int cnt = g_cnt[node];

        float4 s0, s1;
        if (cnt > 0) {
            int sn = g_csr_src[beg];
            const float4* hp = (const float4*)(g_h1 + (long)sn * HID);
            s0 = hp[lane]; s1 = hp[lane + 32];
        }
        for (int e = 0; e < cnt; e++) {
            float4 c0 = s0, c1 = s1;
            if (e + 1 < cnt) {
                int sn = g_csr_src[beg + e + 1];
                const float4* hp = (const float4*)(g_h1 + (long)sn * HID);
                s0 = hp[lane]; s1 = hp[lane + 32];
            }
            float dx = c0.x - d0.x; float d2 = dx * dx;
            dx = c0.y - d0.y; d2 = fmaf(dx, dx, d2);
            dx = c0.z - d0.z; d2 = fmaf(dx, dx, d2);
            dx = c0.w - d0.w; d2 = fmaf(dx, dx, d2);
            dx = c1.x - d1.x; d2 = fmaf(dx, dx, d2);
            dx = c1.y - d1.y; d2 = fmaf(dx, dx, d2);
            dx = c1.z - d1.z; d2 = fmaf(dx, dx, d2);
            dx = c1.w - d1.w; d2 = fmaf(dx, dx, d2);
            #pragma unroll
            for (int o = 16; o > 0; o >>= 1) d2 += __shfl_xor_sync(0xffffffffu, d2, o);
            float w = __expf(-gam * d2);
            a0.x = fmaf(w, c0.x, a0.x); a0.y = fmaf(w, c0.y, a0.y);
            a0.z = fmaf(w, c0.z, a0.z); a0.w = fmaf(w, c0.w, a0.w);
            a1.x = fmaf(w, c1.x, a1.x); a1.y = fmaf(w, c1.y, a1.y);
            a1.z = fmaf(w, c1.z, a1.z); a1.w = fmaf(w, c1.w, a1.w);
            den += w;
        }
        float inv = 1.f / (den + 1e-16f);
        float4 x0 = make_float4(a0.x * inv, a0.y * inv, a0.z * inv, a0.w * inv);
        float4 x1 = make_float4(a1.x * inv, a1.y * inv, a1.z * inv, a1.w * inv);
        float4* xp = (float4*)(g_x1 + (long)node * HID);
        xp[lane] = x0; xp[lane + 32] = x1;
        ps0[0] += x0.x; ps0[1] += x0.y; ps0[2] += x0.z; ps0[3] += x0.w;
        ps1[0] += x1.x; ps1[1] += x1.y; ps1[2] += x1.z; ps1[3] += x1.w;
        pq0[0] += x0.x * x0.x; pq0[1] += x0.y * x0.y; pq0[2] += x0.z * x0.z; pq0[3] += x0.w * x0.w;
        pq1[0] += x1.x * x1.x; pq1[1] += x1.y * x1.y; pq1[2] += x1.z * x1.z; pq1[3] += x1.w * x1.w;
    }

    __shared__ float sm_s[HID], sm_q[HID];
    sm_s[threadIdx.x] = 0.f; sm_q[threadIdx.x] = 0.f;
    __syncthreads();
    #pragma unroll
    for (int j = 0; j < 4; j++) {
        atomicAdd(&sm_s[4 * lane + j], ps0[j]);
        atomicAdd(&sm_s[128 + 4 * lane + j], ps1[j]);
        atomicAdd(&sm_q[4 * lane + j], pq0[j]);
        atomicAdd(&sm_q[128 + 4 * lane + j], pq1[j]);
    }
    __syncthreads();
    atomicAdd(&g_sum1[threadIdx.x], sm_s[threadIdx.x]);
    atomicAdd(&g_sq1[threadIdx.x], sm_q[threadIdx.x]);
}

__global__ void bnprep1_kernel(const float* __restrict__ w, const float* __restrict__ b) {
    int c = threadIdx.x;
    float mean = g_sum1[c] * (1.f / N_NODES);
    float var  = g_sq1[c] * (1.f / N_NODES) - mean * mean;
    float sc = w[c] * rsqrtf(var + 1e-5f);
    g_scale1[c] = sc;
    g_shift1[c] = b[c] - mean * sc;
}

// ---------------- GEMM2: h2 = relu(bn1(x1)) @ W2 + b2 (BN+relu fused in A-load) --
__global__ __launch_bounds__(256) void gemm2_kernel(
    const float* __restrict__ W2, const float* __restrict__ b2)
{
    __shared__ float As[32][68];
    __shared__ float Bs[32][40];
    const int tid = threadIdx.x;
    const int bm = blockIdx.x * 64;
    const int row = tid >> 2;
    const int cg = (tid & 3) * 10;

    float acc[10] = {};

    for (int k0 = 0; k0 < HID; k0 += 32) {
        #pragma unroll
        for (int t = 0; t < 2; t++) {
            int li = tid + t * 256;
            int r = li >> 3;
            int kk = (li & 7) * 4;
            int gr = min(bm + r, N_NODES - 1);
            float4 v = *(const float4*)(g_x1 + (long)gr * HID + k0 + kk);
            int c4 = (k0 + kk) >> 2;
            float4 sc = ((const float4*)g_scale1)[c4];
            float4 sh = ((const float4*)g_shift1)[c4];
            v.x = fmaxf(fmaf(v.x, sc.x, sh.x), 0.f);
            v.y = fmaxf(fmaf(v.y, sc.y, sh.y), 0.f);
            v.z = fmaxf(fmaf(v.z, sc.z, sh.z), 0.f);
            v.w = fmaxf(fmaf(v.w, sc.w, sh.w), 0.f);
            As[kk + 0][r] = v.x; As[kk + 1][r] = v.y;
            As[kk + 2][r] = v.z; As[kk + 3][r] = v.w;
        }
        for (int i = tid; i < 32 * 40; i += 256)
            Bs[i / 40][i % 40] = W2[(long)(k0 + i / 40) * OUT + (i % 40)];
        __syncthreads();

        #pragma unroll
        for (int k = 0; k < 32; k++) {
            float a = As[k][row];
            #pragma unroll
            for (int j = 0; j < 10; j++)
                acc[j] = fmaf(a, Bs[k][cg + j], acc[j]);
        }
        __syncthreads();
    }

    int gr = bm + row;
    if (gr < N_NODES) {
        #pragma unroll
        for (int j = 0; j < 10; j++)
            g_h2[(long)gr * OUT + cg + j] = acc[j] + b2[cg + j];
    }
}

// ---------------- Layer-2 aggregation: CSR, warp-per-node, fused stats -----------
__global__ __launch_bounds__(256) void agg2_kernel(const float* __restrict__ gamma) {
    const int lane = threadIdx.x & 31;
    const int gwarp = (blockIdx.x * 256 + threadIdx.x) >> 5;
    const int nwarps = gridDim.x * 8;
    const float gam = gamma[0];

    float ps[2] = {0, 0}, pq[2] = {0, 0};   // channels 2*lane, 2*lane+1 (lane<20)

    for (int node = gwarp; node < N_NODES; node += nwarps) {
        const float2* hd = (const float2*)(g_h2 + (long)node * OUT);
        float2 d = make_float2(0.f, 0.f);
        if (lane < 20) d = hd[lane];
        float2 a = make_float2(0.f, 0.f);
        float den = 0.f;
        const int beg = g_off[node];
        const int cnt = g_cnt[node];

        float2 sv = make_float2(0.f, 0.f);
        if (cnt > 0) {
            int sn = g_csr_src[beg];
            if (lane < 20) sv = ((const float2*)(g_h2 + (long)sn * OUT))[lane];
        }
        for (int e = 0; e < cnt; e++) {
            float2 c = sv;
            if (e + 1 < cnt) {
                int sn = g_csr_src[beg + e + 1];
                if (lane < 20) sv = ((const float2*)(g_h2 + (long)sn * OUT))[lane];
            }
            float dx = c.x - d.x, dy = c.y - d.y;
            float d2 = (lane < 20) ? fmaf(dx, dx, dy * dy) : 0.f;
            #pragma unroll
            for (int o = 16; o > 0; o >>= 1) d2 += __shfl_xor_sync(0xffffffffu, d2, o);
            float w = __expf(-gam * d2);
            a.x = fmaf(w, c.x, a.x); a.y = fmaf(w, c.y, a.y);
            den += w;
        }
        float inv = 1.f / (den + 1e-16f);
        float2 x = make_float2(a.x * inv, a.y * inv);
        if (lane < 20) {
            ((float2*)(g_x2 + (long)node * OUT))[lane] = x;
            ps[0] += x.x; ps[1] += x.y;
            pq[0] += x.x * x.x; pq[1] += x.y * x.y;
        }
    }

    __shared__ float sm_s[OUT], sm_q[OUT];
    if (threadIdx.x < OUT) { sm_s[threadIdx.x] = 0.f; sm_q[threadIdx.x] = 0.f; }
    __syncthreads();
    if (lane < 20) {
        atomicAdd(&sm_s[2 * lane + 0], ps[0]);
        atomicAdd(&sm_s[2 * lane + 1], ps[1]);
        atomicAdd(&sm_q[2 * lane + 0], pq[0]);
        atomicAdd(&sm_q[2 * lane + 1], pq[1]);
    }
    __syncthreads();
    if (threadIdx.x < OUT) {
        atomicAdd(&g_sum2[threadIdx.x], sm_s[threadIdx.x]);
        atomicAdd(&g_sq2[threadIdx.x], sm_q[threadIdx.x]);
    }
}

__global__ void bnprep2_kernel(const float* __restrict__ w, const float* __restrict__ b) {
    int c = threadIdx.x;
    float mean = g_sum2[c] * (1.f / N_NODES);
    float var  = g_sq2[c] * (1.f / N_NODES) - mean * mean;
    float sc = w[c] * rsqrtf(var + 1e-5f);
    g_scale2[c] = sc;
    g_shift2[c] = b[c] - mean * sc;
}

// ---------------- gather batch nodes, BN2 + relu + log_softmax -------------------
__global__ __launch_bounds__(256) void final_kernel(
    const void* __restrict__ bnodes, float* __restrict__ out)
{
    int warp = (blockIdx.x * 256 + threadIdx.x) >> 5;
    int lane = threadIdx.x & 31;
    if (warp >= N_BATCH) return;
    int node = load_idx(bnodes, warp);
    const float* x = g_x2 + (long)node * OUT;

    float v0 = fmaxf(fmaf(x[lane], g_scale2[lane], g_shift2[lane]), 0.f);
    float v1 = -1e30f;
    if (lane < 8)
        v1 = fmaxf(fmaf(x[32 + lane], g_scale2[32 + lane], g_shift2[32 + lane]), 0.f);

    float m = fmaxf(v0, v1);
    #pragma unroll
    for (int o = 16; o > 0; o >>= 1) m = fmaxf(m, __shfl_xor_sync(0xffffffffu, m, o));
    float e = expf(v0 - m) + (lane < 8 ? expf(v1 - m) : 0.f);
    #pragma unroll
    for (int o = 16; o > 0; o >>= 1) e += __shfl_xor_sync(0xffffffffu, e, o);
    float lz = m + logf(e);

    out[(long)warp * OUT + lane] = v0 - lz;
    if (lane < 8) out[(long)warp * OUT + 32 + lane] = v1 - lz;
}

// ---------------- launcher --------------------------------------------------------
extern "C" void kernel_launch(void* const* d_in, const int* in_sizes, int n_in,
                              void* d_out, int out_size) {
    const float* features = (const float*)d_in[0];
    const void*  edge     = d_in[1];
    const void*  batch    = d_in[2];
    const float* W1 = (const float*)d_in[3];
    const float* b1 = (const float*)d_in[4];
    const float* g1 = (const float*)d_in[5];
    const float* W2 = (const float*)d_in[6];
    const float* b2 = (const float*)d_in[7];
    const float* g2 = (const float*)d_in[8];
    const float* bn1w = (const float*)d_in[9];
    const float* bn1b = (const float*)d_in[10];
    const float* bn2w = (const float*)d_in[11];
    const float* bn2b = (const float*)d_in[12];
    float* out = (float*)d_out;

    detect_kernel<<<1, 64>>>(edge);
    zero_kernel<<<(N_NODES + 255) / 256, 256>>>();

    // CSR build
    hist_kernel<<<(N_EDGES + 255) / 256, 256>>>(edge);
    scan_kernel<<<1, 1024>>>();
    scatter_kernel<<<(N_EDGES + 255) / 256, 256>>>(edge);

    // layer 1
    dim3 gg1((N_NODES + 127) / 128, HID / 128);
    gemm1_kernel<<<gg1, 256>>>(features, W1, b1);
    agg1_kernel<<<1024, 256>>>(g1);
    bnprep1_kernel<<<1, HID>>>(bn1w, bn1b);

    // layer 2
    gemm2_kernel<<<(N_NODES + 63) / 64, 256>>>(W2, b2);
    agg2_kernel<<<512, 256>>>(g2);
    bnprep2_kernel<<<1, OUT>>>(bn2w, bn2b);

    final_kernel<<<(N_BATCH * 32 + 255) / 256, 256>>>(batch, out);
}

// round 6
// speedup vs baseline: 1.6993x; 1.4197x over previous
#include <cuda_runtime.h>
#include <cuda_bf16.h>
#include <stdint.h>
#include <math.h>

#define N_NODES 50000
#define N_EDGES 800000
#define FEAT 256
#define HID 256
#define OUT 40
#define N_BATCH 10000

#define MT_PAD 3128                 // padded m-tiles (16 rows each) -> 50048 rows = 391*128
#define NB_SCAN ((N_NODES + 255) / 256)   // 196 scan blocks

// ---------------- scratch (device globals; no allocation allowed) ----------------
__device__ float g_h1[N_NODES * HID];     // h1 (gemm1 out)
__device__ float g_x1[N_NODES * HID];     // x1 = num1/den1 (pre-BN)
__device__ float g_h2[N_NODES * OUT];     // h2 (gemm2 out)
__device__ float g_x2[N_NODES * OUT];     // x2 = num2/den2 (pre-BN)
__device__ float g_sum1[HID], g_sq1[HID], g_scale1[HID], g_shift1[HID];
__device__ float g_sum2[OUT], g_sq2[OUT], g_scale2[OUT], g_shift2[OUT];
__device__ int   g_is64;

// CSR
__device__ int g_cnt[N_NODES];
__device__ int g_off[N_NODES];
__device__ int g_cur[N_NODES];
__device__ int g_csr_src[N_EDGES];
__device__ int g_bsum[NB_SCAN];
__device__ int g_boff[NB_SCAN];

// bf16-split fragment-major operands for tensor-core GEMM1
__device__ uint4 g_a_hi[MT_PAD * 16 * 32];   // [mtile][ktile][lane] -> 4 a-regs
__device__ uint4 g_a_lo[MT_PAD * 16 * 32];
__device__ uint2 g_w_hi[16 * 32 * 32];       // [ktile][ntile][lane] -> 2 b-regs
__device__ uint2 g_w_lo[16 * 32 * 32];

// ---------------- dtype detection for edge_index / batch_nodes -------------------
__global__ void detect_kernel(const void* ei) {
    if (threadIdx.x == 0) {
        const long long* p = (const long long*)ei;
        int ok64 = 1;
        for (int i = 0; i < 64; i++) {
            long long v = p[i];
            if (v < 0 || v >= (long long)N_NODES) { ok64 = 0; break; }
        }
        g_is64 = ok64;
    }
}

__device__ __forceinline__ int load_idx(const void* p, long i) {
    return g_is64 ? (int)((const long long*)p)[i] : ((const int*)p)[i];
}

// ---------------- zero small accumulators (every launch) -------------------------
__global__ void zero_kernel() {
    int i = blockIdx.x * 256 + threadIdx.x;
    if (i < N_NODES) g_cnt[i] = 0;
    if (i < HID) { g_sum1[i] = 0.f; g_sq1[i] = 0.f; }
    if (i < OUT) { g_sum2[i] = 0.f; g_sq2[i] = 0.f; }
}

// ---------------- CSR build ------------------------------------------------------
__global__ void hist_kernel(const void* __restrict__ ei) {
    int i = blockIdx.x * 256 + threadIdx.x;
    if (i >= N_EDGES) return;
    int dst = load_idx(ei, (long)N_EDGES + i);
    atomicAdd(&g_cnt[dst], 1);
}

// phase 1: per-block sums
__global__ void scan1_kernel() {
    int i = blockIdx.x * 256 + threadIdx.x;
    int v = (i < N_NODES) ? g_cnt[i] : 0;
    #pragma unroll
    for (int o = 16; o > 0; o >>= 1) v += __shfl_xor_sync(0xffffffffu, v, o);
    __shared__ int ws[8];
    if ((threadIdx.x & 31) == 0) ws[threadIdx.x >> 5] = v;
    __syncthreads();
    if (threadIdx.x == 0) {
        int s = 0;
        #pragma unroll
        for (int j = 0; j < 8; j++) s += ws[j];
        g_bsum[blockIdx.x] = s;
    }
}

// phase 2: exclusive scan of block sums (NB_SCAN <= 256)
__global__ void scan2_kernel() {
    __shared__ int sm[256];
    int t = threadIdx.x;
    int v = (t < NB_SCAN) ? g_bsum[t] : 0;
    sm[t] = v;
    __syncthreads();
    for (int o = 1; o < 256; o <<= 1) {
        int u = (t >= o) ? sm[t - o] : 0;
        __syncthreads();
        sm[t] += u;
        __syncthreads();
    }
    if (t < NB_SCAN) g_boff[t] = sm[t] - v;   // exclusive
}

// phase 3: per-block exclusive scan + block offset -> g_off, g_cur
__global__ void scan3_kernel() {
    int i = blockIdx.x * 256 + threadIdx.x;
    int lane = threadIdx.x & 31, wid = threadIdx.x >> 5;
    int v = (i < N_NODES) ? g_cnt[i] : 0;
    int x = v;
    #pragma unroll
    for (int o = 1; o < 32; o <<= 1) {
        int u = __shfl_up_sync(0xffffffffu, x, o);
        if (lane >= o) x += u;
    }
    __shared__ int wt[8];
    if (lane == 31) wt[wid] = x;
    __syncthreads();
    if (threadIdx.x < 8) {
        int y = wt[threadIdx.x];
        int z = y;
        #pragma unroll
        for (int o = 1; o < 8; o <<= 1) {
            int u = __shfl_up_sync(0xffu, z, o);
            if (threadIdx.x >= o) z += u;
        }
        wt[threadIdx.x] = z - y;   // exclusive warp offset
    }
    __syncthreads();
    int excl = x - v + wt[wid] + g_boff[blockIdx.x];
    if (i < N_NODES) { g_off[i] = excl; g_cur[i] = excl; }
}

__global__ void scatter_kernel(const void* __restrict__ ei) {
    int i = blockIdx.x * 256 + threadIdx.x;
    if (i >= N_EDGES) return;
    int src = load_idx(ei, i);
    int dst = load_idx(ei, (long)N_EDGES + i);
    int pos = atomicAdd(&g_cur[dst], 1);
    g_csr_src[pos] = src;
}

// ---------------- bf16 split helpers ----------------------------------------------
__device__ __forceinline__ void split2(float x, float y, unsigned int& h, unsigned int& l) {
    __nv_bfloat162 hb = __floats2bfloat162_rn(x, y);
    float rx = x - __bfloat162float(hb.x);
    float ry = y - __bfloat162float(hb.y);
    __nv_bfloat162 lb = __floats2bfloat162_rn(rx, ry);
    h = *reinterpret_cast<unsigned int*>(&hb);
    l = *reinterpret_cast<unsigned int*>(&lb);
}

// ---------------- prep A: features -> fragment-major bf16 hi/lo -------------------
__global__ void prepA_kernel(const float* __restrict__ A) {
    int gid = blockIdx.x * 256 + threadIdx.x;
    if (gid >= MT_PAD * 16 * 32) return;
    int lane = gid & 31;
    int tile = gid >> 5;
    int kt = tile & 15, mt = tile >> 4;
    int g = lane >> 2, i = lane & 3;
    int r0 = mt * 16 + g;
    int c0 = kt * 16 + 2 * i;
    float v0 = 0.f, v1 = 0.f, v2 = 0.f, v3 = 0.f;
    float v4 = 0.f, v5 = 0.f, v6 = 0.f, v7 = 0.f;
    if (r0 < N_NODES) {
        float2 p = *(const float2*)(A + (long)r0 * FEAT + c0);
        float2 q = *(const float2*)(A + (long)r0 * FEAT + c0 + 8);
        v0 = p.x; v1 = p.y; v4 = q.x; v5 = q.y;
    }
    int r1 = r0 + 8;
    if (r1 < N_NODES) {
        float2 p = *(const float2*)(A + (long)r1 * FEAT + c0);
        float2 q = *(const float2*)(A + (long)r1 * FEAT + c0 + 8);
        v2 = p.x; v3 = p.y; v6 = q.x; v7 = q.y;
    }
    uint4 hi, lo;
    split2(v0, v1, hi.x, lo.x);   // a0: row g,   k 2i..2i+1
    split2(v2, v3, hi.y, lo.y);   // a1: row g+8, k 2i..2i+1
    split2(v4, v5, hi.z, lo.z);   // a2: row g,   k 2i+8..2i+9
    split2(v6, v7, hi.w, lo.w);   // a3: row g+8, k 2i+8..2i+9
    g_a_hi[gid] = hi;
    g_a_lo[gid] = lo;
}

// ---------------- prep W: W1 -> fragment-major bf16 hi/lo --------------------------
__global__ void prepW_kernel(const float* __restrict__ W) {
    int gid = blockIdx.x * 256 + threadIdx.x;
    if (gid >= 16 * 32 * 32) return;
    int lane = gid & 31;
    int tile = gid >> 5;
    int nt = tile & 31, kt = tile >> 5;
    int g = lane >> 2, i = lane & 3;
    int k0 = kt * 16 + 2 * i;
    int n = nt * 8 + g;
    float b00 = W[(long)k0 * HID + n];
    float b01 = W[(long)(k0 + 1) * HID + n];
    float b10 = W[(long)(k0 + 8) * HID + n];
    float b11 = W[(long)(k0 + 9) * HID + n];
    uint2 hi, lo;
    split2(b00, b01, hi.x, lo.x);   // b0: k 2i..2i+1,   n g
    split2(b10, b11, hi.y, lo.y);   // b1: k 2i+8..2i+9, n g
    g_w_hi[gid] = hi;
    g_w_lo[gid] = lo;
}

#define MMA_BF16(c, a, b)                                                      \
    asm volatile("mma.sync.aligned.m16n8k16.row.col.f32.bf16.bf16.f32 "        \
                 "{%0,%1,%2,%3}, {%4,%5,%6,%7}, {%8,%9}, {%0,%1,%2,%3};"       \
                 : "+f"((c)[0]), "+f"((c)[1]), "+f"((c)[2]), "+f"((c)[3])      \
                 : "r"((a).x), "r"((a).y), "r"((a).z), "r"((a).w),             \
                   "r"((b).x), "r"((b).y))

// ---------------- GEMM1 (tensor cores): h1 = features @ W1 + b1 -------------------
__global__ __launch_bounds__(256) void gemm1_tc_kernel(const float* __restrict__ bias) {
    const int w = threadIdx.x >> 5, lane = threadIdx.x & 31;
    const int wm = w & 1, wn = w >> 1;           // 2 x 4 warp grid
    const int mt0 = blockIdx.x * 8 + wm * 4;     // 4 m-tiles (64 rows) per warp
    const int nt0 = blockIdx.y * 16 + wn * 4;    // 4 n-tiles (32 cols) per warp

    float acc[4][4][4];
    #pragma unroll
    for (int mi = 0; mi < 4; mi++)
        #pragma unroll
        for (int ni = 0; ni < 4; ni++)
            #pragma unroll
            for (int r = 0; r < 4; r++) acc[mi][ni][r] = 0.f;

    #pragma unroll 1
    for (int kt = 0; kt < 16; kt++) {
        uint4 ah[4], al[4];
        #pragma unroll
        for (int mi = 0; mi < 4; mi++) {
            long t = ((long)(mt0 + mi) * 16 + kt) * 32 + lane;
            ah[mi] = g_a_hi[t];
            al[mi] = g_a_lo[t];
        }
        uint2 bh[4], bl[4];
        #pragma unroll
        for (int ni = 0; ni < 4; ni++) {
            int t = (kt * 32 + nt0 + ni) * 32 + lane;
            bh[ni] = g_w_hi[t];
            bl[ni] = g_w_lo[t];
        }
        #pragma unroll
        for (int mi = 0; mi < 4; mi++)
            #pragma unroll
            for (int ni = 0; ni < 4; ni++) {
                MMA_BF16(acc[mi][ni], ah[mi], bh[ni]);
                MMA_BF16(acc[mi][ni], ah[mi], bl[ni]);
                MMA_BF16(acc[mi][ni], al[mi], bh[ni]);
            }
    }

    const int g = lane >> 2, i = lane & 3;
    #pragma unroll
    for (int mi = 0; mi < 4; mi++) {
        int r0 = (mt0 + mi) * 16 + g;
        int r1 = r0 + 8;
        #pragma unroll
        for (int ni = 0; ni < 4; ni++) {
            int c = (nt0 + ni) * 8 + 2 * i;
            float bx = bias[c], by = bias[c + 1];
            if (r0 < N_NODES) {
                float2 o = make_float2(acc[mi][ni][0] + bx, acc[mi][ni][1] + by);
                *(float2*)&g_h1[(long)r0 * HID + c] = o;
            }
            if (r1 < N_NODES) {
                float2 o = make_float2(acc[mi][ni][2] + bx, acc[mi][ni][3] + by);
                *(float2*)&g_h1[(long)r1 * HID + c] = o;
            }
        }
    }
}

// ---------------- Layer-1 aggregation: CSR, warp-per-node -------------------------
__global__ __launch_bounds__(256) void agg1_kernel(const float* __restrict__ gamma) {
    const int lane = threadIdx.x & 31;
    const int gwarp = (blockIdx.x * 256 + threadIdx.x) >> 5;
    const int nwarps = gridDim.x * 8;
    const float gam = gamma[0];

    float ps0[4] = {0, 0, 0, 0}, ps1[4] = {0, 0, 0, 0};
    float pq0[4] = {0, 0, 0, 0}, pq1[4] = {0, 0, 0, 0};

    for (int node = gwarp; node < N_NODES; node += nwarps) {
        const float4* hd = (const float4*)(g_h1 + (long)node * HID);
        float4 d0 = hd[lane], d1 = hd[lane + 32];
        float4 a0 = make_float4(0.f, 0.f, 0.f, 0.f);
        float4 a1 = make_float4(0.f, 0.f, 0.f, 0.f);
        float den = 0.f;
        const int beg = g_off[node];
        const int cnt = g_cnt[node];

        float4 s0, s1;
        if (cnt > 0) {
            int sn = g_csr_src[beg];
            const float4* hp = (const float4*)(g_h1 + (long)sn * HID);
            s0 = hp[lane]; s1 = hp[lane + 32];
        }
        for (int e = 0; e < cnt; e++) {
            float4 c0 = s0, c1 = s1;
            if (e + 1 < cnt) {
                int sn = g_csr_src[beg + e + 1];
                const float4* hp = (const float4*)(g_h1 + (long)sn * HID);
                s0 = hp[lane]; s1 = hp[lane + 32];
            }
            float dx = c0.x - d0.x; float d2 = dx * dx;
            dx = c0.y - d0.y; d2 = fmaf(dx, dx, d2);
            dx = c0.z - d0.z; d2 = fmaf(dx, dx, d2);
            dx = c0.w - d0.w; d2 = fmaf(dx, dx, d2);
            dx = c1.x - d1.x; d2 = fmaf(dx, dx, d2);
            dx = c1.y - d1.y; d2 = fmaf(dx, dx, d2);
            dx = c1.z - d1.z; d2 = fmaf(dx, dx, d2);
            dx = c1.w - d1.w; d2 = fmaf(dx, dx, d2);
            #pragma unroll
            for (int o = 16; o > 0; o >>= 1) d2 += __shfl_xor_sync(0xffffffffu, d2, o);
            float w = __expf(-gam * d2);
            a0.x = fmaf(w, c0.x, a0.x); a0.y = fmaf(w, c0.y, a0.y);
            a0.z = fmaf(w, c0.z, a0.z); a0.w = fmaf(w, c0.w, a0.w);
            a1.x = fmaf(w, c1.x, a1.x); a1.y = fmaf(w, c1.y, a1.y);
            a1.z = fmaf(w, c1.z, a1.z); a1.w = fmaf(w, c1.w, a1.w);
            den += w;
        }
        float inv = 1.f / (den + 1e-16f);
        float4 x0 = make_float4(a0.x * inv, a0.y * inv, a0.z * inv, a0.w * inv);
        float4 x1 = make_float4(a1.x * inv, a1.y * inv, a1.z * inv, a1.w * inv);
        float4* xp = (float4*)(g_x1 + (long)node * HID);
        xp[lane] = x0; xp[lane + 32] = x1;
        ps0[0] += x0.x; ps0[1] += x0.y; ps0[2] += x0.z; ps0[3] += x0.w;
        ps1[0] += x1.x; ps1[1] += x1.y; ps1[2] += x1.z; ps1[3] += x1.w;
        pq0[0] += x0.x * x0.x; pq0[1] += x0.y * x0.y; pq0[2] += x0.z * x0.z; pq0[3] += x0.w * x0.w;
        pq1[0] += x1.x * x1.x; pq1[1] += x1.y * x1.y; pq1[2] += x1.z * x1.z; pq1[3] += x1.w * x1.w;
    }

    __shared__ float sm_s[HID], sm_q[HID];
    sm_s[threadIdx.x] = 0.f; sm_q[threadIdx.x] = 0.f;
    __syncthreads();
    #pragma unroll
    for (int j = 0; j < 4; j++) {
        atomicAdd(&sm_s[4 * lane + j], ps0[j]);
        atomicAdd(&sm_s[128 + 4 * lane + j], ps1[j]);
        atomicAdd(&sm_q[4 * lane + j], pq0[j]);
        atomicAdd(&sm_q[128 + 4 * lane + j], pq1[j]);
    }
    __syncthreads();
    atomicAdd(&g_sum1[threadIdx.x], sm_s[threadIdx.x]);
    atomicAdd(&g_sq1[threadIdx.x], sm_q[threadIdx.x]);
}

__global__ void bnprep1_kernel(const float* __restrict__ w, const float* __restrict__ b) {
    int c = threadIdx.x;
    float mean = g_sum1[c] * (1.f / N_NODES);
    float var  = g_sq1[c] * (1.f / N_NODES) - mean * mean;
    float sc = w[c] * rsqrtf(var + 1e-5f);
    g_scale1[c] = sc;
    g_shift1[c] = b[c] - mean * sc;
}

// ---------------- GEMM2: h2 = relu(bn1(x1)) @ W2 + b2 -----------------------------
__global__ __launch_bounds__(256) void gemm2_kernel(
    const float* __restrict__ W2, const float* __restrict__ b2)
{
    __shared__ float As[32][68];
    __shared__ float Bs[32][40];
    const int tid = threadIdx.x;
    const int bm = blockIdx.x * 64;
    const int row = tid >> 2;
    const int cg = (tid & 3) * 10;

    float acc[10] = {};

    for (int k0 = 0; k0 < HID; k0 += 32) {
        #pragma unroll
        for (int t = 0; t < 2; t++) {
            int li = tid + t * 256;
            int r = li >> 3;
            int kk = (li & 7) * 4;
            int gr = min(bm + r, N_NODES - 1);
            float4 v = *(const float4*)(g_x1 + (long)gr * HID + k0 + kk);
            int c4 = (k0 + kk) >> 2;
            float4 sc = ((const float4*)g_scale1)[c4];
            float4 sh = ((const float4*)g_shift1)[c4];
            v.x = fmaxf(fmaf(v.x, sc.x, sh.x), 0.f);
            v.y = fmaxf(fmaf(v.y, sc.y, sh.y), 0.f);
            v.z = fmaxf(fmaf(v.z, sc.z, sh.z), 0.f);
            v.w = fmaxf(fmaf(v.w, sc.w, sh.w), 0.f);
            As[kk + 0][r] = v.x; As[kk + 1][r] = v.y;
            As[kk + 2][r] = v.z; As[kk + 3][r] = v.w;
        }
        for (int i = tid; i < 32 * 40; i += 256)
            Bs[i / 40][i % 40] = W2[(long)(k0 + i / 40) * OUT + (i % 40)];
        __syncthreads();

        #pragma unroll
        for (int k = 0; k < 32; k++) {
            float a = As[k][row];
            #pragma unroll
            for (int j = 0; j < 10; j++)
                acc[j] = fmaf(a, Bs[k][cg + j], acc[j]);
        }
        __syncthreads();
    }

    int gr = bm + row;
    if (gr < N_NODES) {
        #pragma unroll
        for (int j = 0; j < 10; j++)
            g_h2[(long)gr * OUT + cg + j] = acc[j] + b2[cg + j];
    }
}

// ---------------- Layer-2 aggregation --------------------------------------------
__global__ __launch_bounds__(256) void agg2_kernel(const float* __restrict__ gamma) {
    const int lane = threadIdx.x & 31;
    const int gwarp = (blockIdx.x * 256 + threadIdx.x) >> 5;
    const int nwarps = gridDim.x * 8;
    const float gam = gamma[0];

    float ps[2] = {0, 0}, pq[2] = {0, 0};

    for (int node = gwarp; node < N_NODES; node += nwarps) {
        const float2* hd = (const float2*)(g_h2 + (long)node * OUT);
        float2 d = make_float2(0.f, 0.f);
        if (lane < 20) d = hd[lane];
        float2 a = make_float2(0.f, 0.f);
        float den = 0.f;
        const int beg = g_off[node];
        const int cnt = g_cnt[node];

        float2 sv = make_float2(0.f, 0.f);
        if (cnt > 0) {
            int sn = g_csr_src[beg];
            if (lane < 20) sv = ((const float2*)(g_h2 + (long)sn * OUT))[lane];
        }
        for (int e = 0; e < cnt; e++) {
            float2 c = sv;
            if (e + 1 < cnt) {
                int sn = g_csr_src[beg + e + 1];
                if (lane < 20) sv = ((const float2*)(g_h2 + (long)sn * OUT))[lane];
            }
            float dx = c.x - d.x, dy = c.y - d.y;
            float d2 = (lane < 20) ? fmaf(dx, dx, dy * dy) : 0.f;
            #pragma unroll
            for (int o = 16; o > 0; o >>= 1) d2 += __shfl_xor_sync(0xffffffffu, d2, o);
            float w = __expf(-gam * d2);
            a.x = fmaf(w, c.x, a.x); a.y = fmaf(w, c.y, a.y);
            den += w;
        }
        float inv = 1.f / (den + 1e-16f);
        float2 x = make_float2(a.x * inv, a.y * inv);
        if (lane < 20) {
            ((float2*)(g_x2 + (long)node * OUT))[lane] = x;
            ps[0] += x.x; ps[1] += x.y;
            pq[0] += x.x * x.x; pq[1] += x.y * x.y;
        }
    }

    __shared__ float sm_s[OUT], sm_q[OUT];
    if (threadIdx.x < OUT) { sm_s[threadIdx.x] = 0.f; sm_q[threadIdx.x] = 0.f; }
    __syncthreads();
    if (lane < 20) {
        atomicAdd(&sm_s[2 * lane + 0], ps[0]);
        atomicAdd(&sm_s[2 * lane + 1], ps[1]);
        atomicAdd(&sm_q[2 * lane + 0], pq[0]);
        atomicAdd(&sm_q[2 * lane + 1], pq[1]);
    }
    __syncthreads();
    if (threadIdx.x < OUT) {
        atomicAdd(&g_sum2[threadIdx.x], sm_s[threadIdx.x]);
        atomicAdd(&g_sq2[threadIdx.x], sm_q[threadIdx.x]);
    }
}

__global__ void bnprep2_kernel(const float* __restrict__ w, const float* __restrict__ b) {
    int c = threadIdx.x;
    float mean = g_sum2[c] * (1.f / N_NODES);
    float var  = g_sq2[c] * (1.f / N_NODES) - mean * mean;
    float sc = w[c] * rsqrtf(var + 1e-5f);
    g_scale2[c] = sc;
    g_shift2[c] = b[c] - mean * sc;
}

// ---------------- gather batch nodes, BN2 + relu + log_softmax -------------------
__global__ __launch_bounds__(256) void final_kernel(
    const void* __restrict__ bnodes, float* __restrict__ out)
{
    int warp = (blockIdx.x * 256 + threadIdx.x) >> 5;
    int lane = threadIdx.x & 31;
    if (warp >= N_BATCH) return;
    int node = load_idx(bnodes, warp);
    const float* x = g_x2 + (long)node * OUT;

    float v0 = fmaxf(fmaf(x[lane], g_scale2[lane], g_shift2[lane]), 0.f);
    float v1 = -1e30f;
    if (lane < 8)
        v1 = fmaxf(fmaf(x[32 + lane], g_scale2[32 + lane], g_shift2[32 + lane]), 0.f);

    float m = fmaxf(v0, v1);
    #pragma unroll
    for (int o = 16; o > 0; o >>= 1) m = fmaxf(m, __shfl_xor_sync(0xffffffffu, m, o));
    float e = expf(v0 - m) + (lane < 8 ? expf(v1 - m) : 0.f);
    #pragma unroll
    for (int o = 16; o > 0; o >>= 1) e += __shfl_xor_sync(0xffffffffu, e, o);
    float lz = m + logf(e);

    out[(long)warp * OUT + lane] = v0 - lz;
    if (lane < 8) out[(long)warp * OUT + 32 + lane] = v1 - lz;
}

// ---------------- launcher --------------------------------------------------------
extern "C" void kernel_launch(void* const* d_in, const int* in_sizes, int n_in,
                              void* d_out, int out_size) {
    const float* features = (const float*)d_in[0];
    const void*  edge     = d_in[1];
    const void*  batch    = d_in[2];
    const float* W1 = (const float*)d_in[3];
    const float* b1 = (const float*)d_in[4];
    const float* g1 = (const float*)d_in[5];
    const float* W2 = (const float*)d_in[6];
    const float* b2 = (const float*)d_in[7];
    const float* g2 = (const float*)d_in[8];
    const float* bn1w = (const float*)d_in[9];
    const float* bn1b = (const float*)d_in[10];
    const float* bn2w = (const float*)d_in[11];
    const float* bn2b = (const float*)d_in[12];
    float* out = (float*)d_out;

    detect_kernel<<<1, 64>>>(edge);
    zero_kernel<<<(N_NODES + 255) / 256, 256>>>();

    // operand prep for tensor-core GEMM1
    prepA_kernel<<<(MT_PAD * 16 * 32 + 255) / 256, 256>>>(features);
    prepW_kernel<<<(16 * 32 * 32 + 255) / 256, 256>>>(W1);

    // CSR build
    hist_kernel<<<(N_EDGES + 255) / 256, 256>>>(edge);
    scan1_kernel<<<NB_SCAN, 256>>>();
    scan2_kernel<<<1, 256>>>();
    scan3_kernel<<<NB_SCAN, 256>>>();
    scatter_kernel<<<(N_EDGES + 255) / 256, 256>>>(edge);

    // layer 1
    dim3 gg1(MT_PAD / 8, 2);
    gemm1_tc_kernel<<<gg1, 256>>>(b1);
    agg1_kernel<<<1024, 256>>>(g1);
    bnprep1_kernel<<<1, HID>>>(bn1w, bn1b);

    // layer 2
    gemm2_kernel<<<(N_NODES + 63) / 64, 256>>>(W2, b2);
    agg2_kernel<<<512, 256>>>(g2);
    bnprep2_kernel<<<1, OUT>>>(bn2w, bn2b);

    final_kernel<<<(N_BATCH * 32 + 255) / 256, 256>>>(batch, out);
}

// round 7
// speedup vs baseline: 2.0733x; 1.2201x over previous
#include <cuda_runtime.h>
#include <cuda_bf16.h>
#include <stdint.h>
#include <math.h>

#define N_NODES 50000
#define N_EDGES 800000
#define FEAT 256
#define HID 256
#define OUT 40
#define N_BATCH 10000

#define MT_PAD 3128                 // padded m-tiles (16 rows each) -> 50048 rows
#define NB_SCAN ((N_NODES + 255) / 256)   // 196 scan blocks

// ---------------- scratch (device globals; no allocation allowed) ----------------
__device__ float g_h1[N_NODES * HID];     // h1 (gemm1 out)
__device__ float g_x1[N_NODES * HID];     // x1 = num1/den1 (pre-BN)
__device__ float g_h2[N_NODES * OUT];     // h2 (gemm2 out)
__device__ float g_x2[N_NODES * OUT];     // x2 = num2/den2 (pre-BN)
__device__ float g_sum1[HID], g_sq1[HID], g_scale1[HID], g_shift1[HID];
__device__ float g_sum2[OUT], g_sq2[OUT], g_scale2[OUT], g_shift2[OUT];
__device__ int   g_is64;

// CSR
__device__ int g_cnt[N_NODES];
__device__ int g_off[N_NODES];
__device__ int g_cur[N_NODES];
__device__ int g_csr_src[N_EDGES];
__device__ int g_bsum[NB_SCAN];
__device__ int g_boff[NB_SCAN];

// bf16-split fragment-major operands for tensor-core GEMMs
__device__ uint4 g_a_hi[MT_PAD * 16 * 32];   // [mtile][ktile][lane] -> 4 a-regs
__device__ uint4 g_a_lo[MT_PAD * 16 * 32];
__device__ uint2 g_w_hi[16 * 32 * 32];       // W1: [ktile][ntile][lane] -> 2 b-regs
__device__ uint2 g_w_lo[16 * 32 * 32];
__device__ uint2 g_w2_hi[16 * 5 * 32];       // W2: [ktile][ntile][lane]
__device__ uint2 g_w2_lo[16 * 5 * 32];

// ---------------- detect dtype + zero accumulators (merged) ----------------------
__global__ void detect_zero_kernel(const void* ei) {
    int i = blockIdx.x * 256 + threadIdx.x;
    if (i == 0) {
        const long long* p = (const long long*)ei;
        int ok64 = 1;
        for (int j = 0; j < 64; j++) {
            long long v = p[j];
            if (v < 0 || v >= (long long)N_NODES) { ok64 = 0; break; }
        }
        g_is64 = ok64;
    }
    if (i < N_NODES) g_cnt[i] = 0;
    if (i < HID) { g_sum1[i] = 0.f; g_sq1[i] = 0.f; }
    if (i < OUT) { g_sum2[i] = 0.f; g_sq2[i] = 0.f; }
}

__device__ __forceinline__ int load_idx(const void* p, long i) {
    return g_is64 ? (int)((const long long*)p)[i] : ((const int*)p)[i];
}

// ---------------- CSR build ------------------------------------------------------
__global__ void hist_kernel(const void* __restrict__ ei) {
    int i = blockIdx.x * 256 + threadIdx.x;
    if (i >= N_EDGES) return;
    int dst = load_idx(ei, (long)N_EDGES + i);
    atomicAdd(&g_cnt[dst], 1);
}

__global__ void scan1_kernel() {
    int i = blockIdx.x * 256 + threadIdx.x;
    int v = (i < N_NODES) ? g_cnt[i] : 0;
    #pragma unroll
    for (int o = 16; o > 0; o >>= 1) v += __shfl_xor_sync(0xffffffffu, v, o);
    __shared__ int ws[8];
    if ((threadIdx.x & 31) == 0) ws[threadIdx.x >> 5] = v;
    __syncthreads();
    if (threadIdx.x == 0) {
        int s = 0;
        #pragma unroll
        for (int j = 0; j < 8; j++) s += ws[j];
        g_bsum[blockIdx.x] = s;
    }
}

__global__ void scan2_kernel() {
    __shared__ int sm[256];
    int t = threadIdx.x;
    int v = (t < NB_SCAN) ? g_bsum[t] : 0;
    sm[t] = v;
    __syncthreads();
    for (int o = 1; o < 256; o <<= 1) {
        int u = (t >= o) ? sm[t - o] : 0;
        __syncthreads();
        sm[t] += u;
        __syncthreads();
    }
    if (t < NB_SCAN) g_boff[t] = sm[t] - v;   // exclusive
}

__global__ void scan3_kernel() {
    int i = blockIdx.x * 256 + threadIdx.x;
    int lane = threadIdx.x & 31, wid = threadIdx.x >> 5;
    int v = (i < N_NODES) ? g_cnt[i] : 0;
    int x = v;
    #pragma unroll
    for (int o = 1; o < 32; o <<= 1) {
        int u = __shfl_up_sync(0xffffffffu, x, o);
        if (lane >= o) x += u;
    }
    __shared__ int wt[8];
    if (lane == 31) wt[wid] = x;
    __syncthreads();
    if (threadIdx.x < 8) {
        int y = wt[threadIdx.x];
        int z = y;
        #pragma unroll
        for (int o = 1; o < 8; o <<= 1) {
            int u = __shfl_up_sync(0xffu, z, o);
            if (threadIdx.x >= o) z += u;
        }
        wt[threadIdx.x] = z - y;
    }
    __syncthreads();
    int excl = x - v + wt[wid] + g_boff[blockIdx.x];
    if (i < N_NODES) { g_off[i] = excl; g_cur[i] = excl; }
}

__global__ void scatter_kernel(const void* __restrict__ ei) {
    int i = blockIdx.x * 256 + threadIdx.x;
    if (i >= N_EDGES) return;
    int src = load_idx(ei, i);
    int dst = load_idx(ei, (long)N_EDGES + i);
    int pos = atomicAdd(&g_cur[dst], 1);
    g_csr_src[pos] = src;
}

// ---------------- bf16 split helpers ----------------------------------------------
__device__ __forceinline__ void split2(float x, float y, unsigned int& h, unsigned int& l) {
    __nv_bfloat162 hb = __floats2bfloat162_rn(x, y);
    float rx = x - __bfloat162float(hb.x);
    float ry = y - __bfloat162float(hb.y);
    __nv_bfloat162 lb = __floats2bfloat162_rn(rx, ry);
    h = *reinterpret_cast<unsigned int*>(&hb);
    l = *reinterpret_cast<unsigned int*>(&lb);
}

// ---------------- prep A: features -> fragment-major bf16 hi/lo -------------------
__global__ void prepA_kernel(const float* __restrict__ A) {
    int gid = blockIdx.x * 256 + threadIdx.x;
    if (gid >= MT_PAD * 16 * 32) return;
    int lane = gid & 31;
    int tile = gid >> 5;
    int kt = tile & 15, mt = tile >> 4;
    int g = lane >> 2, i = lane & 3;
    int r0 = mt * 16 + g;
    int c0 = kt * 16 + 2 * i;
    float v0 = 0.f, v1 = 0.f, v2 = 0.f, v3 = 0.f;
    float v4 = 0.f, v5 = 0.f, v6 = 0.f, v7 = 0.f;
    if (r0 < N_NODES) {
        float2 p = *(const float2*)(A + (long)r0 * FEAT + c0);
        float2 q = *(const float2*)(A + (long)r0 * FEAT + c0 + 8);
        v0 = p.x; v1 = p.y; v4 = q.x; v5 = q.y;
    }
    int r1 = r0 + 8;
    if (r1 < N_NODES) {
        float2 p = *(const float2*)(A + (long)r1 * FEAT + c0);
        float2 q = *(const float2*)(A + (long)r1 * FEAT + c0 + 8);
        v2 = p.x; v3 = p.y; v6 = q.x; v7 = q.y;
    }
    uint4 hi, lo;
    split2(v0, v1, hi.x, lo.x);
    split2(v2, v3, hi.y, lo.y);
    split2(v4, v5, hi.z, lo.z);
    split2(v6, v7, hi.w, lo.w);
    g_a_hi[gid] = hi;
    g_a_lo[gid] = lo;
}

// ---------------- prep W1 / W2 -> fragment-major bf16 hi/lo ------------------------
__global__ void prepW_kernel(const float* __restrict__ W) {
    int gid = blockIdx.x * 256 + threadIdx.x;
    if (gid >= 16 * 32 * 32) return;
    int lane = gid & 31;
    int tile = gid >> 5;
    int nt = tile & 31, kt = tile >> 5;
    int g = lane >> 2, i = lane & 3;
    int k0 = kt * 16 + 2 * i;
    int n = nt * 8 + g;
    float b00 = W[(long)k0 * HID + n];
    float b01 = W[(long)(k0 + 1) * HID + n];
    float b10 = W[(long)(k0 + 8) * HID + n];
    float b11 = W[(long)(k0 + 9) * HID + n];
    uint2 hi, lo;
    split2(b00, b01, hi.x, lo.x);
    split2(b10, b11, hi.y, lo.y);
    g_w_hi[gid] = hi;
    g_w_lo[gid] = lo;
}

__global__ void prepW2_kernel(const float* __restrict__ W) {
    int gid = blockIdx.x * 256 + threadIdx.x;
    if (gid >= 16 * 5 * 32) return;
    int lane = gid & 31;
    int tile = gid >> 5;
    int nt = tile % 5, kt = tile / 5;
    int g = lane >> 2, i = lane & 3;
    int k0 = kt * 16 + 2 * i;
    int n = nt * 8 + g;
    float b00 = W[(long)k0 * OUT + n];
    float b01 = W[(long)(k0 + 1) * OUT + n];
    float b10 = W[(long)(k0 + 8) * OUT + n];
    float b11 = W[(long)(k0 + 9) * OUT + n];
    uint2 hi, lo;
    split2(b00, b01, hi.x, lo.x);
    split2(b10, b11, hi.y, lo.y);
    g_w2_hi[gid] = hi;
    g_w2_lo[gid] = lo;
}

#define MMA_BF16(c, a, b)                                                      \
    asm volatile("mma.sync.aligned.m16n8k16.row.col.f32.bf16.bf16.f32 "        \
                 "{%0,%1,%2,%3}, {%4,%5,%6,%7}, {%8,%9}, {%0,%1,%2,%3};"       \
                 : "+f"((c)[0]), "+f"((c)[1]), "+f"((c)[2]), "+f"((c)[3])      \
                 : "r"((a).x), "r"((a).y), "r"((a).z), "r"((a).w),             \
                   "r"((b).x), "r"((b).y))

// ---------------- GEMM1 (tensor cores): h1 = features @ W1 + b1 -------------------
__global__ __launch_bounds__(256) void gemm1_tc_kernel(const float* __restrict__ bias) {
    const int w = threadIdx.x >> 5, lane = threadIdx.x & 31;
    const int wm = w & 1, wn = w >> 1;
    const int mt0 = blockIdx.x * 8 + wm * 4;
    const int nt0 = blockIdx.y * 16 + wn * 4;

    float acc[4][4][4];
    #pragma unroll
    for (int mi = 0; mi < 4; mi++)
        #pragma unroll
        for (int ni = 0; ni < 4; ni++)
            #pragma unroll
            for (int r = 0; r < 4; r++) acc[mi][ni][r] = 0.f;

    #pragma unroll 1
    for (int kt = 0; kt < 16; kt++) {
        uint4 ah[4], al[4];
        #pragma unroll
        for (int mi = 0; mi < 4; mi++) {
            long t = ((long)(mt0 + mi) * 16 + kt) * 32 + lane;
            ah[mi] = g_a_hi[t];
            al[mi] = g_a_lo[t];
        }
        uint2 bh[4], bl[4];
        #pragma unroll
        for (int ni = 0; ni < 4; ni++) {
            int t = (kt * 32 + nt0 + ni) * 32 + lane;
            bh[ni] = g_w_hi[t];
            bl[ni] = g_w_lo[t];
        }
        #pragma unroll
        for (int mi = 0; mi < 4; mi++)
            #pragma unroll
            for (int ni = 0; ni < 4; ni++) {
                MMA_BF16(acc[mi][ni], ah[mi], bh[ni]);
                MMA_BF16(acc[mi][ni], ah[mi], bl[ni]);
                MMA_BF16(acc[mi][ni], al[mi], bh[ni]);
            }
    }

    const int g = lane >> 2, i = lane & 3;
    #pragma unroll
    for (int mi = 0; mi < 4; mi++) {
        int r0 = (mt0 + mi) * 16 + g;
        int r1 = r0 + 8;
        #pragma unroll
        for (int ni = 0; ni < 4; ni++) {
            int c = (nt0 + ni) * 8 + 2 * i;
            float bx = bias[c], by = bias[c + 1];
            if (r0 < N_NODES) {
                float2 o = make_float2(acc[mi][ni][0] + bx, acc[mi][ni][1] + by);
                *(float2*)&g_h1[(long)r0 * HID + c] = o;
            }
            if (r1 < N_NODES) {
                float2 o = make_float2(acc[mi][ni][2] + bx, acc[mi][ni][3] + by);
                *(float2*)&g_h1[(long)r1 * HID + c] = o;
            }
        }
    }
}

// ---------------- Layer-1 aggregation: CSR, warp-per-node -------------------------
__global__ __launch_bounds__(256) void agg1_kernel(const float* __restrict__ gamma) {
    const int lane = threadIdx.x & 31;
    const int gwarp = (blockIdx.x * 256 + threadIdx.x) >> 5;
    const int nwarps = gridDim.x * 8;
    const float gam = gamma[0];

    float ps0[4] = {0, 0, 0, 0}, ps1[4] = {0, 0, 0, 0};
    float pq0[4] = {0, 0, 0, 0}, pq1[4] = {0, 0, 0, 0};

    for (int node = gwarp; node < N_NODES; node += nwarps) {
        const float4* hd = (const float4*)(g_h1 + (long)node * HID);
        float4 d0 = hd[lane], d1 = hd[lane + 32];
        float4 a0 = make_float4(0.f, 0.f, 0.f, 0.f);
        float4 a1 = make_float4(0.f, 0.f, 0.f, 0.f);
        float den = 0.f;
        const int beg = g_off[node];
        const int cnt = g_cnt[node];

        float4 s0, s1;
        if (cnt > 0) {
            int sn = g_csr_src[beg];
            const float4* hp = (const float4*)(g_h1 + (long)sn * HID);
            s0 = hp[lane]; s1 = hp[lane + 32];
        }
        for (int e = 0; e < cnt; e++) {
            float4 c0 = s0, c1 = s1;
            if (e + 1 < cnt) {
                int sn = g_csr_src[beg + e + 1];
                const float4* hp = (const float4*)(g_h1 + (long)sn * HID);
                s0 = hp[lane]; s1 = hp[lane + 32];
            }
            float dx = c0.x - d0.x; float d2 = dx * dx;
            dx = c0.y - d0.y; d2 = fmaf(dx, dx, d2);
            dx = c0.z - d0.z; d2 = fmaf(dx, dx, d2);
            dx = c0.w - d0.w; d2 = fmaf(dx, dx, d2);
            dx = c1.x - d1.x; d2 = fmaf(dx, dx, d2);
            dx = c1.y - d1.y; d2 = fmaf(dx, dx, d2);
            dx = c1.z - d1.z; d2 = fmaf(dx, dx, d2);
            dx = c1.w - d1.w; d2 = fmaf(dx, dx, d2);
            #pragma unroll
            for (int o = 16; o > 0; o >>= 1) d2 += __shfl_xor_sync(0xffffffffu, d2, o);
            float w = __expf(-gam * d2);
            a0.x = fmaf(w, c0.x, a0.x); a0.y = fmaf(w, c0.y, a0.y);
            a0.z = fmaf(w, c0.z, a0.z); a0.w = fmaf(w, c0.w, a0.w);
            a1.x = fmaf(w, c1.x, a1.x); a1.y = fmaf(w, c1.y, a1.y);
            a1.z = fmaf(w, c1.z, a1.z); a1.w = fmaf(w, c1.w, a1.w);
            den += w;
        }
        float inv = 1.f / (den + 1e-16f);
        float4 x0 = make_float4(a0.x * inv, a0.y * inv, a0.z * inv, a0.w * inv);
        float4 x1 = make_float4(a1.x * inv, a1.y * inv, a1.z * inv, a1.w * inv);
        float4* xp = (float4*)(g_x1 + (long)node * HID);
        xp[lane] = x0; xp[lane + 32] = x1;
        ps0[0] += x0.x; ps0[1] += x0.y; ps0[2] += x0.z; ps0[3] += x0.w;
        ps1[0] += x1.x; ps1[1] += x1.y; ps1[2] += x1.z; ps1[3] += x1.w;
        pq0[0] += x0.x * x0.x; pq0[1] += x0.y * x0.y; pq0[2] += x0.z * x0.z; pq0[3] += x0.w * x0.w;
        pq1[0] += x1.x * x1.x; pq1[1] += x1.y * x1.y; pq1[2] += x1.z * x1.z; pq1[3] += x1.w * x1.w;
    }

    __shared__ float sm_s[HID], sm_q[HID];
    sm_s[threadIdx.x] = 0.f; sm_q[threadIdx.x] = 0.f;
    __syncthreads();
    #pragma unroll
    for (int j = 0; j < 4; j++) {
        atomicAdd(&sm_s[4 * lane + j], ps0[j]);
        atomicAdd(&sm_s[128 + 4 * lane + j], ps1[j]);
        atomicAdd(&sm_q[4 * lane + j], pq0[j]);
        atomicAdd(&sm_q[128 + 4 * lane + j], pq1[j]);
    }
    __syncthreads();
    atomicAdd(&g_sum1[threadIdx.x], sm_s[threadIdx.x]);
    atomicAdd(&g_sq1[threadIdx.x], sm_q[threadIdx.x]);
}

__global__ void bnprep1_kernel(const float* __restrict__ w, const float* __restrict__ b) {
    int c = threadIdx.x;
    float mean = g_sum1[c] * (1.f / N_NODES);
    float var  = g_sq1[c] * (1.f / N_NODES) - mean * mean;
    float sc = w[c] * rsqrtf(var + 1e-5f);
    g_scale1[c] = sc;
    g_shift1[c] = b[c] - mean * sc;
}

// ---------------- GEMM2 (tensor cores): h2 = relu(bn1(x1)) @ W2 + b2 ---------------
// BN + relu + bf16 split applied inline on the A-operand loads.
__global__ __launch_bounds__(256) void gemm2_tc_kernel(const float* __restrict__ b2) {
    __shared__ float s_sc[HID], s_sh[HID];
    if (threadIdx.x < 128) {
        s_sc[threadIdx.x] = g_scale1[threadIdx.x];
        s_sc[threadIdx.x + 128] = g_scale1[threadIdx.x + 128];
        s_sh[threadIdx.x] = g_shift1[threadIdx.x];
        s_sh[threadIdx.x + 128] = g_shift1[threadIdx.x + 128];
    }
    __syncthreads();

    const int w = threadIdx.x >> 5, lane = threadIdx.x & 31;
    const int g = lane >> 2, i = lane & 3;
    const int m_base = blockIdx.x * 512 + w * 64;   // 4 m-tiles per warp

    float acc[4][5][4];
    #pragma unroll
    for (int mi = 0; mi < 4; mi++)
        #pragma unroll
        for (int ni = 0; ni < 5; ni++)
            #pragma unroll
            for (int r = 0; r < 4; r++) acc[mi][ni][r] = 0.f;

    #pragma unroll 1
    for (int kt = 0; kt < 16; kt++) {
        const int c0 = kt * 16 + 2 * i;
        // BN params for the 4 columns this lane touches
        float sc0 = s_sc[c0], sc1 = s_sc[c0 + 1], sc8 = s_sc[c0 + 8], sc9 = s_sc[c0 + 9];
        float sh0 = s_sh[c0], sh1 = s_sh[c0 + 1], sh8 = s_sh[c0 + 8], sh9 = s_sh[c0 + 9];

        uint2 bh[5], bl[5];
        #pragma unroll
        for (int ni = 0; ni < 5; ni++) {
            int t = (kt * 5 + ni) * 32 + lane;
            bh[ni] = g_w2_hi[t];
            bl[ni] = g_w2_lo[t];
        }

        uint4 ah[4], al[4];
        #pragma unroll
        for (int mi = 0; mi < 4; mi++) {
            int r0 = min(m_base + mi * 16 + g, N_NODES - 1);
            int r1 = min(m_base + mi * 16 + g + 8, N_NODES - 1);
            const float* p0 = g_x1 + (long)r0 * HID + c0;
            const float* p1 = g_x1 + (long)r1 * HID + c0;
            float2 u0 = *(const float2*)p0;       // r0, c0..c0+1
            float2 u2 = *(const float2*)(p0 + 8); // r0, c0+8..c0+9
            float2 u1 = *(const float2*)p1;       // r1
            float2 u3 = *(const float2*)(p1 + 8);
            u0.x = fmaxf(fmaf(u0.x, sc0, sh0), 0.f);
            u0.y = fmaxf(fmaf(u0.y, sc1, sh1), 0.f);
            u1.x = fmaxf(fmaf(u1.x, sc0, sh0), 0.f);
            u1.y = fmaxf(fmaf(u1.y, sc1, sh1), 0.f);
            u2.x = fmaxf(fmaf(u2.x, sc8, sh8), 0.f);
            u2.y = fmaxf(fmaf(u2.y, sc9, sh9), 0.f);
            u3.x = fmaxf(fmaf(u3.x, sc8, sh8), 0.f);
            u3.y = fmaxf(fmaf(u3.y, sc9, sh9), 0.f);
            split2(u0.x, u0.y, ah[mi].x, al[mi].x);
            split2(u1.x, u1.y, ah[mi].y, al[mi].y);
            split2(u2.x, u2.y, ah[mi].z, al[mi].z);
            split2(u3.x, u3.y, ah[mi].w, al[mi].w);
        }

        #pragma unroll
        for (int mi = 0; mi < 4; mi++)
            #pragma unroll
            for (int ni = 0; ni < 5; ni++) {
                MMA_BF16(acc[mi][ni], ah[mi], bh[ni]);
                MMA_BF16(acc[mi][ni], ah[mi], bl[ni]);
                MMA_BF16(acc[mi][ni], al[mi], bh[ni]);
            }
    }

    #pragma unroll
    for (int mi = 0; mi < 4; mi++) {
        int r0 = m_base + mi * 16 + g;
        int r1 = r0 + 8;
        #pragma unroll
        for (int ni = 0; ni < 5; ni++) {
            int c = ni * 8 + 2 * i;
            float bx = b2[c], by = b2[c + 1];
            if (r0 < N_NODES) {
                float2 o = make_float2(acc[mi][ni][0] + bx, acc[mi][ni][1] + by);
                *(float2*)&g_h2[(long)r0 * OUT + c] = o;
            }
            if (r1 < N_NODES) {
                float2 o = make_float2(acc[mi][ni][2] + bx, acc[mi][ni][3] + by);
                *(float2*)&g_h2[(long)r1 * OUT + c] = o;
            }
        }
    }
}

// ---------------- Layer-2 aggregation --------------------------------------------
__global__ __launch_bounds__(256) void agg2_kernel(const float* __restrict__ gamma) {
    const int lane = threadIdx.x & 31;
    const int gwarp = (blockIdx.x * 256 + threadIdx.x) >> 5;
    const int nwarps = gridDim.x * 8;
    const float gam = gamma[0];

    float ps[2] = {0, 0}, pq[2] = {0, 0};

    for (int node = gwarp; node < N_NODES; node += nwarps) {
        const float2* hd = (const float2*)(g_h2 + (long)node * OUT);
        float2 d = make_float2(0.f, 0.f);
        if (lane < 20) d = hd[lane];
        float2 a = make_float2(0.f, 0.f);
        float den = 0.f;
        const int beg = g_off[node];
        const int cnt = g_cnt[node];

        float2 sv = make_float2(0.f, 0.f);
        if (cnt > 0) {
            int sn = g_csr_src[beg];
            if (lane < 20) sv = ((const float2*)(g_h2 + (long)sn * OUT))[lane];
        }
        for (int e = 0; e < cnt; e++) {
            float2 c = sv;
            if (e + 1 < cnt) {
                int sn = g_csr_src[beg + e + 1];
                if (lane < 20) sv = ((const float2*)(g_h2 + (long)sn * OUT))[lane];
            }
            float dx = c.x - d.x, dy = c.y - d.y;
            float d2 = (lane < 20) ? fmaf(dx, dx, dy * dy) : 0.f;
            #pragma unroll
            for (int o = 16; o > 0; o >>= 1) d2 += __shfl_xor_sync(0xffffffffu, d2, o);
            float w = __expf(-gam * d2);
            a.x = fmaf(w, c.x, a.x); a.y = fmaf(w, c.y, a.y);
            den += w;
        }
        float inv = 1.f / (den + 1e-16f);
        float2 x = make_float2(a.x * inv, a.y * inv);
        if (lane < 20) {
            ((float2*)(g_x2 + (long)node * OUT))[lane] = x;
            ps[0] += x.x; ps[1] += x.y;
            pq[0] += x.x * x.x; pq[1] += x.y * x.y;
        }
    }

    __shared__ float sm_s[OUT], sm_q[OUT];
    if (threadIdx.x < OUT) { sm_s[threadIdx.x] = 0.f; sm_q[threadIdx.x] = 0.f; }
    __syncthreads();
    if (lane < 20) {
        atomicAdd(&sm_s[2 * lane + 0], ps[0]);
        atomicAdd(&sm_s[2 * lane + 1], ps[1]);
        atomicAdd(&sm_q[2 * lane + 0], pq[0]);
        atomicAdd(&sm_q[2 * lane + 1], pq[1]);
    }
    __syncthreads();
    if (threadIdx.x < OUT) {
        atomicAdd(&g_sum2[threadIdx.x], sm_s[threadIdx.x]);
        atomicAdd(&g_sq2[threadIdx.x], sm_q[threadIdx.x]);
    }
}

__global__ void bnprep2_kernel(const float* __restrict__ w, const float* __restrict__ b) {
    int c = threadIdx.x;
    float mean = g_sum2[c] * (1.f / N_NODES);
    float var  = g_sq2[c] * (1.f / N_NODES) - mean * mean;
    float sc = w[c] * rsqrtf(var + 1e-5f);
    g_scale2[c] = sc;
    g_shift2[c] = b[c] - mean * sc;
}

// ---------------- gather batch nodes, BN2 + relu + log_softmax -------------------
__global__ __launch_bounds__(256) void final_kernel(
    const void* __restrict__ bnodes, float* __restrict__ out)
{
    int warp = (blockIdx.x * 256 + threadIdx.x) >> 5;
    int lane = threadIdx.x & 31;
    if (warp >= N_BATCH) return;
    int node = load_idx(bnodes, warp);
    const float* x = g_x2 + (long)node * OUT;

    float v0 = fmaxf(fmaf(x[lane], g_scale2[lane], g_shift2[lane]), 0.f);
    float v1 = -1e30f;
    if (lane < 8)
        v1 = fmaxf(fmaf(x[32 + lane], g_scale2[32 + lane], g_shift2[32 + lane]), 0.f);

    float m = fmaxf(v0, v1);
    #pragma unroll
    for (int o = 16; o > 0; o >>= 1) m = fmaxf(m, __shfl_xor_sync(0xffffffffu, m, o));
    float e = expf(v0 - m) + (lane < 8 ? expf(v1 - m) : 0.f);
    #pragma unroll
    for (int o = 16; o > 0; o >>= 1) e += __shfl_xor_sync(0xffffffffu, e, o);
    float lz = m + logf(e);

    out[(long)warp * OUT + lane] = v0 - lz;
    if (lane < 8) out[(long)warp * OUT + 32 + lane] = v1 - lz;
}

// ---------------- launcher --------------------------------------------------------
extern "C" void kernel_launch(void* const* d_in, const int* in_sizes, int n_in,
                              void* d_out, int out_size) {
    const float* features = (const float*)d_in[0];
    const void*  edge     = d_in[1];
    const void*  batch    = d_in[2];
    const float* W1 = (const float*)d_in[3];
    const float* b1 = (const float*)d_in[4];
    const float* g1 = (const float*)d_in[5];
    const float* W2 = (const float*)d_in[6];
    const float* b2 = (const float*)d_in[7];
    const float* g2 = (const float*)d_in[8];
    const float* bn1w = (const float*)d_in[9];
    const float* bn1b = (const float*)d_in[10];
    const float* bn2w = (const float*)d_in[11];
    const float* bn2b = (const float*)d_in[12];
    float* out = (float*)d_out;

    detect_zero_kernel<<<NB_SCAN, 256>>>(edge);

    // operand prep
    prepA_kernel<<<(MT_PAD * 16 * 32 + 255) / 256, 256>>>(features);
    prepW_kernel<<<(16 * 32 * 32 + 255) / 256, 256>>>(W1);
    prepW2_kernel<<<(16 * 5 * 32 + 255) / 256, 256>>>(W2);

    // CSR build
    hist_kernel<<<(N_EDGES + 255) / 256, 256>>>(edge);
    scan1_kernel<<<NB_SCAN, 256>>>();
    scan2_kernel<<<1, 256>>>();
    scan3_kernel<<<NB_SCAN, 256>>>();
    scatter_kernel<<<(N_EDGES + 255) / 256, 256>>>(edge);

    // layer 1
    dim3 gg1(MT_PAD / 8, 2);
    gemm1_tc_kernel<<<gg1, 256>>>(b1);
    agg1_kernel<<<2048, 256>>>(g1);
    bnprep1_kernel<<<1, HID>>>(bn1w, bn1b);

    // layer 2
    gemm2_tc_kernel<<<(N_NODES + 511) / 512, 256>>>(b2);
    agg2_kernel<<<1024, 256>>>(g2);
    bnprep2_kernel<<<1, OUT>>>(bn2w, bn2b);

    final_kernel<<<(N_BATCH * 32 + 255) / 256, 256>>>(batch, out);
}

// round 8
// speedup vs baseline: 2.1356x; 1.0300x over previous
#include <cuda_runtime.h>
#include <cuda_bf16.h>
#include <stdint.h>
#include <math.h>

#define N_NODES 50000
#define N_EDGES 800000
#define FEAT 256
#define HID 256
#define OUT 40
#define N_BATCH 10000

#define NB_SCAN ((N_NODES + 255) / 256)   // 196 scan blocks

// ---------------- scratch (device globals; no allocation allowed) ----------------
__device__ float g_h1[N_NODES * HID];     // h1 (gemm1 out)
__device__ float g_x1[N_NODES * HID];     // x1 = num1/den1 (pre-BN)
__device__ float g_h2[N_NODES * OUT];     // h2 (gemm2 out)
__device__ float g_x2[N_NODES * OUT];     // x2 = num2/den2 (pre-BN)
__device__ float g_sum1[HID], g_sq1[HID], g_scale1[HID], g_shift1[HID];
__device__ float g_sum2[OUT], g_sq2[OUT], g_scale2[OUT], g_shift2[OUT];
__device__ int   g_is64;

// CSR
__device__ int g_cnt[N_NODES];
__device__ int g_off[N_NODES];
__device__ int g_cur[N_NODES];
__device__ int g_csr_src[N_EDGES];
__device__ int g_bsum[NB_SCAN];
__device__ int g_boff[NB_SCAN];

// bf16-split fragment-major weights
__device__ uint2 g_w_hi[16 * 32 * 32];       // W1: [ktile][ntile][lane]
__device__ uint2 g_w_lo[16 * 32 * 32];
__device__ uint2 g_w2_hi[16 * 5 * 32];       // W2: [ktile][ntile][lane]
__device__ uint2 g_w2_lo[16 * 5 * 32];

// ---------------- detect dtype + zero accumulators (merged) ----------------------
__global__ void detect_zero_kernel(const void* ei) {
    int i = blockIdx.x * 256 + threadIdx.x;
    if (i == 0) {
        const long long* p = (const long long*)ei;
        int ok64 = 1;
        for (int j = 0; j < 64; j++) {
            long long v = p[j];
            if (v < 0 || v >= (long long)N_NODES) { ok64 = 0; break; }
        }
        g_is64 = ok64;
    }
    if (i < N_NODES) g_cnt[i] = 0;
    if (i < HID) { g_sum1[i] = 0.f; g_sq1[i] = 0.f; }
    if (i < OUT) { g_sum2[i] = 0.f; g_sq2[i] = 0.f; }
}

__device__ __forceinline__ int load_idx(const void* p, long i) {
    return g_is64 ? (int)((const long long*)p)[i] : ((const int*)p)[i];
}

// ---------------- CSR build ------------------------------------------------------
__global__ void hist_kernel(const void* __restrict__ ei) {
    int i = blockIdx.x * 256 + threadIdx.x;
    if (i >= N_EDGES) return;
    int dst = load_idx(ei, (long)N_EDGES + i);
    atomicAdd(&g_cnt[dst], 1);
}

__global__ void scan1_kernel() {
    int i = blockIdx.x * 256 + threadIdx.x;
    int v = (i < N_NODES) ? g_cnt[i] : 0;
    #pragma unroll
    for (int o = 16; o > 0; o >>= 1) v += __shfl_xor_sync(0xffffffffu, v, o);
    __shared__ int ws[8];
    if ((threadIdx.x & 31) == 0) ws[threadIdx.x >> 5] = v;
    __syncthreads();
    if (threadIdx.x == 0) {
        int s = 0;
        #pragma unroll
        for (int j = 0; j < 8; j++) s += ws[j];
        g_bsum[blockIdx.x] = s;
    }
}

__global__ void scan2_kernel() {
    __shared__ int sm[256];
    int t = threadIdx.x;
    int v = (t < NB_SCAN) ? g_bsum[t] : 0;
    sm[t] = v;
    __syncthreads();
    for (int o = 1; o < 256; o <<= 1) {
        int u = (t >= o) ? sm[t - o] : 0;
        __syncthreads();
        sm[t] += u;
        __syncthreads();
    }
    if (t < NB_SCAN) g_boff[t] = sm[t] - v;   // exclusive
}

__global__ void scan3_kernel() {
    int i = blockIdx.x * 256 + threadIdx.x;
    int lane = threadIdx.x & 31, wid = threadIdx.x >> 5;
    int v = (i < N_NODES) ? g_cnt[i] : 0;
    int x = v;
    #pragma unroll
    for (int o = 1; o < 32; o <<= 1) {
        int u = __shfl_up_sync(0xffffffffu, x, o);
        if (lane >= o) x += u;
    }
    __shared__ int wt[8];
    if (lane == 31) wt[wid] = x;
    __syncthreads();
    if (threadIdx.x < 8) {
        int y = wt[threadIdx.x];
        int z = y;
        #pragma unroll
        for (int o = 1; o < 8; o <<= 1) {
            int u = __shfl_up_sync(0xffu, z, o);
            if (threadIdx.x >= o) z += u;
        }
        wt[threadIdx.x] = z - y;
    }
    __syncthreads();
    int excl = x - v + wt[wid] + g_boff[blockIdx.x];
    if (i < N_NODES) { g_off[i] = excl; g_cur[i] = excl; }
}

__global__ void scatter_kernel(const void* __restrict__ ei) {
    int i = blockIdx.x * 256 + threadIdx.x;
    if (i >= N_EDGES) return;
    int src = load_idx(ei, i);
    int dst = load_idx(ei, (long)N_EDGES + i);
    int pos = atomicAdd(&g_cur[dst], 1);
    g_csr_src[pos] = src;
}

// ---------------- bf16 split helpers ----------------------------------------------
__device__ __forceinline__ void split2(float x, float y, unsigned int& h, unsigned int& l) {
    __nv_bfloat162 hb = __floats2bfloat162_rn(x, y);
    float rx = x - __bfloat162float(hb.x);
    float ry = y - __bfloat162float(hb.y);
    __nv_bfloat162 lb = __floats2bfloat162_rn(rx, ry);
    h = *reinterpret_cast<unsigned int*>(&hb);
    l = *reinterpret_cast<unsigned int*>(&lb);
}

// ---------------- prep W1 / W2 -> fragment-major bf16 hi/lo ------------------------
__global__ void prepW_kernel(const float* __restrict__ W) {
    int gid = blockIdx.x * 256 + threadIdx.x;
    if (gid >= 16 * 32 * 32) return;
    int lane = gid & 31;
    int tile = gid >> 5;
    int nt = tile & 31, kt = tile >> 5;
    int g = lane >> 2, i = lane & 3;
    int k0 = kt * 16 + 2 * i;
    int n = nt * 8 + g;
    float b00 = W[(long)k0 * HID + n];
    float b01 = W[(long)(k0 + 1) * HID + n];
    float b10 = W[(long)(k0 + 8) * HID + n];
    float b11 = W[(long)(k0 + 9) * HID + n];
    uint2 hi, lo;
    split2(b00, b01, hi.x, lo.x);
    split2(b10, b11, hi.y, lo.y);
    g_w_hi[gid] = hi;
    g_w_lo[gid] = lo;
}

__global__ void prepW2_kernel(const float* __restrict__ W) {
    int gid = blockIdx.x * 256 + threadIdx.x;
    if (gid >= 16 * 5 * 32) return;
    int lane = gid & 31;
    int tile = gid >> 5;
    int nt = tile % 5, kt = tile / 5;
    int g = lane >> 2, i = lane & 3;
    int k0 = kt * 16 + 2 * i;
    int n = nt * 8 + g;
    float b00 = W[(long)k0 * OUT + n];
    float b01 = W[(long)(k0 + 1) * OUT + n];
    float b10 = W[(long)(k0 + 8) * OUT + n];
    float b11 = W[(long)(k0 + 9) * OUT + n];
    uint2 hi, lo;
    split2(b00, b01, hi.x, lo.x);
    split2(b10, b11, hi.y, lo.y);
    g_w2_hi[gid] = hi;
    g_w2_lo[gid] = lo;
}

#define MMA_BF16(c, a, b)                                                      \
    asm volatile("mma.sync.aligned.m16n8k16.row.col.f32.bf16.bf16.f32 "        \
                 "{%0,%1,%2,%3}, {%4,%5,%6,%7}, {%8,%9}, {%0,%1,%2,%3};"       \
                 : "+f"((c)[0]), "+f"((c)[1]), "+f"((c)[2]), "+f"((c)[3])      \
                 : "r"((a).x), "r"((a).y), "r"((a).z), "r"((a).w),             \
                   "r"((b).x), "r"((b).y))

// ---------------- GEMM1 (tensor cores, inline A split): h1 = A @ W1 + b1 ----------
__global__ __launch_bounds__(256) void gemm1_tc_kernel(
    const float* __restrict__ A, const float* __restrict__ bias)
{
    const int w = threadIdx.x >> 5, lane = threadIdx.x & 31;
    const int wm = w & 1, wn = w >> 1;            // 2 x 4 warp grid
    const int g = lane >> 2, i = lane & 3;
    const int m_base = blockIdx.x * 128 + wm * 64;   // 4 m-tiles (64 rows) per warp
    const int nt0 = blockIdx.y * 16 + wn * 4;        // 4 n-tiles (32 cols) per warp

    float acc[4][4][4];
    #pragma unroll
    for (int mi = 0; mi < 4; mi++)
        #pragma unroll
        for (int ni = 0; ni < 4; ni++)
            #pragma unroll
            for (int r = 0; r < 4; r++) acc[mi][ni][r] = 0.f;

    #pragma unroll 1
    for (int kt = 0; kt < 16; kt++) {
        const int c0 = kt * 16 + 2 * i;

        uint2 bh[4], bl[4];
        #pragma unroll
        for (int ni = 0; ni < 4; ni++) {
            int t = (kt * 32 + nt0 + ni) * 32 + lane;
            bh[ni] = g_w_hi[t];
            bl[ni] = g_w_lo[t];
        }

        uint4 ah[4], al[4];
        #pragma unroll
        for (int mi = 0; mi < 4; mi++) {
            int r0 = min(m_base + mi * 16 + g, N_NODES - 1);
            int r1 = min(m_base + mi * 16 + g + 8, N_NODES - 1);
            const float* p0 = A + (long)r0 * FEAT + c0;
            const float* p1 = A + (long)r1 * FEAT + c0;
            float2 u0 = *(const float2*)p0;
            float2 u2 = *(const float2*)(p0 + 8);
            float2 u1 = *(const float2*)p1;
            float2 u3 = *(const float2*)(p1 + 8);
            split2(u0.x, u0.y, ah[mi].x, al[mi].x);
            split2(u1.x, u1.y, ah[mi].y, al[mi].y);
            split2(u2.x, u2.y, ah[mi].z, al[mi].z);
            split2(u3.x, u3.y, ah[mi].w, al[mi].w);
        }

        #pragma unroll
        for (int mi = 0; mi < 4; mi++)
            #pragma unroll
            for (int ni = 0; ni < 4; ni++) {
                MMA_BF16(acc[mi][ni], ah[mi], bh[ni]);
                MMA_BF16(acc[mi][ni], ah[mi], bl[ni]);
                MMA_BF16(acc[mi][ni], al[mi], bh[ni]);
            }
    }

    #pragma unroll
    for (int mi = 0; mi < 4; mi++) {
        int r0 = m_base + mi * 16 + g;
        int r1 = r0 + 8;
        #pragma unroll
        for (int ni = 0; ni < 4; ni++) {
            int c = (nt0 + ni) * 8 + 2 * i;
            float bx = bias[c], by = bias[c + 1];
            if (r0 < N_NODES) {
                float2 o = make_float2(acc[mi][ni][0] + bx, acc[mi][ni][1] + by);
                *(float2*)&g_h1[(long)r0 * HID + c] = o;
            }
            if (r1 < N_NODES) {
                float2 o = make_float2(acc[mi][ni][2] + bx, acc[mi][ni][3] + by);
                *(float2*)&g_h1[(long)r1 * HID + c] = o;
            }
        }
    }
}

// ---------------- Layer-1 aggregation: CSR, warp-per-node -------------------------
__global__ __launch_bounds__(256) void agg1_kernel(const float* __restrict__ gamma) {
    const int lane = threadIdx.x & 31;
    const int gwarp = (blockIdx.x * 256 + threadIdx.x) >> 5;
    const int nwarps = gridDim.x * 8;
    const float gam = gamma[0];

    float ps0[4] = {0, 0, 0, 0}, ps1[4] = {0, 0, 0, 0};
    float pq0[4] = {0, 0, 0, 0}, pq1[4] = {0, 0, 0, 0};

    for (int node = gwarp; node < N_NODES; node += nwarps) {
        const float4* hd = (const float4*)(g_h1 + (long)node * HID);
        float4 d0 = hd[lane], d1 = hd[lane + 32];
        float4 a0 = make_float4(0.f, 0.f, 0.f, 0.f);
        float4 a1 = make_float4(0.f, 0.f, 0.f, 0.f);
        float den = 0.f;
        const int beg = g_off[node];
        const int cnt = g_cnt[node];

        float4 s0, s1;
        if (cnt > 0) {
            int sn = g_csr_src[beg];
            const float4* hp = (const float4*)(g_h1 + (long)sn * HID);
            s0 = hp[lane]; s1 = hp[lane + 32];
        }
        for (int e = 0; e < cnt; e++) {
            float4 c0 = s0, c1 = s1;
            if (e + 1 < cnt) {
                int sn = g_csr_src[beg + e + 1];
                const float4* hp = (const float4*)(g_h1 + (long)sn * HID);
                s0 = hp[lane]; s1 = hp[lane + 32];
            }
            float dx = c0.x - d0.x; float d2 = dx * dx;
            dx = c0.y - d0.y; d2 = fmaf(dx, dx, d2);
            dx = c0.z - d0.z; d2 = fmaf(dx, dx, d2);
            dx = c0.w - d0.w; d2 = fmaf(dx, dx, d2);
            dx = c1.x - d1.x; d2 = fmaf(dx, dx, d2);
            dx = c1.y - d1.y; d2 = fmaf(dx, dx, d2);
            dx = c1.z - d1.z; d2 = fmaf(dx, dx, d2);
            dx = c1.w - d1.w; d2 = fmaf(dx, dx, d2);
            #pragma unroll
            for (int o = 16; o > 0; o >>= 1) d2 += __shfl_xor_sync(0xffffffffu, d2, o);
            float w = __expf(-gam * d2);
            a0.x = fmaf(w, c0.x, a0.x); a0.y = fmaf(w, c0.y, a0.y);
            a0.z = fmaf(w, c0.z, a0.z); a0.w = fmaf(w, c0.w, a0.w);
            a1.x = fmaf(w, c1.x, a1.x); a1.y = fmaf(w, c1.y, a1.y);
            a1.z = fmaf(w, c1.z, a1.z); a1.w = fmaf(w, c1.w, a1.w);
            den += w;
        }
        float inv = 1.f / (den + 1e-16f);
        float4 x0 = make_float4(a0.x * inv, a0.y * inv, a0.z * inv, a0.w * inv);
        float4 x1 = make_float4(a1.x * inv, a1.y * inv, a1.z * inv, a1.w * inv);
        float4* xp = (float4*)(g_x1 + (long)node * HID);
        xp[lane] = x0; xp[lane + 32] = x1;
        ps0[0] += x0.x; ps0[1] += x0.y; ps0[2] += x0.z; ps0[3] += x0.w;
        ps1[0] += x1.x; ps1[1] += x1.y; ps1[2] += x1.z; ps1[3] += x1.w;
        pq0[0] += x0.x * x0.x; pq0[1] += x0.y * x0.y; pq0[2] += x0.z * x0.z; pq0[3] += x0.w * x0.w;
        pq1[0] += x1.x * x1.x; pq1[1] += x1.y * x1.y; pq1[2] += x1.z * x1.z; pq1[3] += x1.w * x1.w;
    }

    __shared__ float sm_s[HID], sm_q[HID];
    sm_s[threadIdx.x] = 0.f; sm_q[threadIdx.x] = 0.f;
    __syncthreads();
    #pragma unroll
    for (int j = 0; j < 4; j++) {
        atomicAdd(&sm_s[4 * lane + j], ps0[j]);
        atomicAdd(&sm_s[128 + 4 * lane + j], ps1[j]);
        atomicAdd(&sm_q[4 * lane + j], pq0[j]);
        atomicAdd(&sm_q[128 + 4 * lane + j], pq1[j]);
    }
    __syncthreads();
    atomicAdd(&g_sum1[threadIdx.x], sm_s[threadIdx.x]);
    atomicAdd(&g_sq1[threadIdx.x], sm_q[threadIdx.x]);
}

__global__ void bnprep1_kernel(const float* __restrict__ w, const float* __restrict__ b) {
    int c = threadIdx.x;
    float mean = g_sum1[c] * (1.f / N_NODES);
    float var  = g_sq1[c] * (1.f / N_NODES) - mean * mean;
    float sc = w[c] * rsqrtf(var + 1e-5f);
    g_scale1[c] = sc;
    g_shift1[c] = b[c] - mean * sc;
}

// ---------------- GEMM2 (tensor cores): h2 = relu(bn1(x1)) @ W2 + b2 ---------------
__global__ __launch_bounds__(256) void gemm2_tc_kernel(const float* __restrict__ b2) {
    __shared__ float s_sc[HID], s_sh[HID];
    if (threadIdx.x < 128) {
        s_sc[threadIdx.x] = g_scale1[threadIdx.x];
        s_sc[threadIdx.x + 128] = g_scale1[threadIdx.x + 128];
        s_sh[threadIdx.x] = g_shift1[threadIdx.x];
        s_sh[threadIdx.x + 128] = g_shift1[threadIdx.x + 128];
    }
    __syncthreads();

    const int w = threadIdx.x >> 5, lane = threadIdx.x & 31;
    const int g = lane >> 2, i = lane & 3;
    const int m_base = blockIdx.x * 512 + w * 64;

    float acc[4][5][4];
    #pragma unroll
    for (int mi = 0; mi < 4; mi++)
        #pragma unroll
        for (int ni = 0; ni < 5; ni++)
            #pragma unroll
            for (int r = 0; r < 4; r++) acc[mi][ni][r] = 0.f;

    #pragma unroll 1
    for (int kt = 0; kt < 16; kt++) {
        const int c0 = kt * 16 + 2 * i;
        float sc0 = s_sc[c0], sc1 = s_sc[c0 + 1], sc8 = s_sc[c0 + 8], sc9 = s_sc[c0 + 9];
        float sh0 = s_sh[c0], sh1 = s_sh[c0 + 1], sh8 = s_sh[c0 + 8], sh9 = s_sh[c0 + 9];

        uint2 bh[5], bl[5];
        #pragma unroll
        for (int ni = 0; ni < 5; ni++) {
            int t = (kt * 5 + ni) * 32 + lane;
            bh[ni] = g_w2_hi[t];
            bl[ni] = g_w2_lo[t];
        }

        uint4 ah[4], al[4];
        #pragma unroll
        for (int mi = 0; mi < 4; mi++) {
            int r0 = min(m_base + mi * 16 + g, N_NODES - 1);
            int r1 = min(m_base + mi * 16 + g + 8, N_NODES - 1);
            const float* p0 = g_x1 + (long)r0 * HID + c0;
            const float* p1 = g_x1 + (long)r1 * HID + c0;
            float2 u0 = *(const float2*)p0;
            float2 u2 = *(const float2*)(p0 + 8);
            float2 u1 = *(const float2*)p1;
            float2 u3 = *(const float2*)(p1 + 8);
            u0.x = fmaxf(fmaf(u0.x, sc0, sh0), 0.f);
            u0.y = fmaxf(fmaf(u0.y, sc1, sh1), 0.f);
            u1.x = fmaxf(fmaf(u1.x, sc0, sh0), 0.f);
            u1.y = fmaxf(fmaf(u1.y, sc1, sh1), 0.f);
            u2.x = fmaxf(fmaf(u2.x, sc8, sh8), 0.f);
            u2.y = fmaxf(fmaf(u2.y, sc9, sh9), 0.f);
            u3.x = fmaxf(fmaf(u3.x, sc8, sh8), 0.f);
            u3.y = fmaxf(fmaf(u3.y, sc9, sh9), 0.f);
            split2(u0.x, u0.y, ah[mi].x, al[mi].x);
            split2(u1.x, u1.y, ah[mi].y, al[mi].y);
            split2(u2.x, u2.y, ah[mi].z, al[mi].z);
            split2(u3.x, u3.y, ah[mi].w, al[mi].w);
        }

        #pragma unroll
        for (int mi = 0; mi < 4; mi++)
            #pragma unroll
            for (int ni = 0; ni < 5; ni++) {
                MMA_BF16(acc[mi][ni], ah[mi], bh[ni]);
                MMA_BF16(acc[mi][ni], ah[mi], bl[ni]);
                MMA_BF16(acc[mi][ni], al[mi], bh[ni]);
            }
    }

    #pragma unroll
    for (int mi = 0; mi < 4; mi++) {
        int r0 = m_base + mi * 16 + g;
        int r1 = r0 + 8;
        #pragma unroll
        for (int ni = 0; ni < 5; ni++) {
            int c = ni * 8 + 2 * i;
            float bx = b2[c], by = b2[c + 1];
            if (r0 < N_NODES) {
                float2 o = make_float2(acc[mi][ni][0] + bx, acc[mi][ni][1] + by);
                *(float2*)&g_h2[(long)r0 * OUT + c] = o;
            }
            if (r1 < N_NODES) {
                float2 o = make_float2(acc[mi][ni][2] + bx, acc[mi][ni][3] + by);
                *(float2*)&g_h2[(long)r1 * OUT + c] = o;
            }
        }
    }
}

// ---------------- Layer-2 aggregation --------------------------------------------
__global__ __launch_bounds__(256) void agg2_kernel(const float* __restrict__ gamma) {
    const int lane = threadIdx.x & 31;
    const int gwarp = (blockIdx.x * 256 + threadIdx.x) >> 5;
    const int nwarps = gridDim.x * 8;
    const float gam = gamma[0];

    float ps[2] = {0, 0}, pq[2] = {0, 0};

    for (int node = gwarp; node < N_NODES; node += nwarps) {
        const float2* hd = (const float2*)(g_h2 + (long)node * OUT);
        float2 d = make_float2(0.f, 0.f);
        if (lane < 20) d = hd[lane];
        float2 a = make_float2(0.f, 0.f);
        float den = 0.f;
        const int beg = g_off[node];
        const int cnt = g_cnt[node];

        float2 sv = make_float2(0.f, 0.f);
        if (cnt > 0) {
            int sn = g_csr_src[beg];
            if (lane < 20) sv = ((const float2*)(g_h2 + (long)sn * OUT))[lane];
        }
        for (int e = 0; e < cnt; e++) {
            float2 c = sv;
            if (e + 1 < cnt) {
                int sn = g_csr_src[beg + e + 1];
                if (lane < 20) sv = ((const float2*)(g_h2 + (long)sn * OUT))[lane];
            }
            float dx = c.x - d.x, dy = c.y - d.y;
            float d2 = (lane < 20) ? fmaf(dx, dx, dy * dy) : 0.f;
            #pragma unroll
            for (int o = 16; o > 0; o >>= 1) d2 += __shfl_xor_sync(0xffffffffu, d2, o);
            float w = __expf(-gam * d2);
            a.x = fmaf(w, c.x, a.x); a.y = fmaf(w, c.y, a.y);
            den += w;
        }
        float inv = 1.f / (den + 1e-16f);
        float2 x = make_float2(a.x * inv, a.y * inv);
        if (lane < 20) {
            ((float2*)(g_x2 + (long)node * OUT))[lane] = x;
            ps[0] += x.x; ps[1] += x.y;
            pq[0] += x.x * x.x; pq[1] += x.y * x.y;
        }
    }

    __shared__ float sm_s[OUT], sm_q[OUT];
    if (threadIdx.x < OUT) { sm_s[threadIdx.x] = 0.f; sm_q[threadIdx.x] = 0.f; }
    __syncthreads();
    if (lane < 20) {
        atomicAdd(&sm_s[2 * lane + 0], ps[0]);
        atomicAdd(&sm_s[2 * lane + 1], ps[1]);
        atomicAdd(&sm_q[2 * lane + 0], pq[0]);
        atomicAdd(&sm_q[2 * lane + 1], pq[1]);
    }
    __syncthreads();
    if (threadIdx.x < OUT) {
        atomicAdd(&g_sum2[threadIdx.x], sm_s[threadIdx.x]);
        atomicAdd(&g_sq2[threadIdx.x], sm_q[threadIdx.x]);
    }
}

__global__ void bnprep2_kernel(const float* __restrict__ w, const float* __restrict__ b) {
    int c = threadIdx.x;
    float mean = g_sum2[c] * (1.f / N_NODES);
    float var  = g_sq2[c] * (1.f / N_NODES) - mean * mean;
    float sc = w[c] * rsqrtf(var + 1e-5f);
    g_scale2[c] = sc;
    g_shift2[c] = b[c] - mean * sc;
}

// ---------------- gather batch nodes, BN2 + relu + log_softmax -------------------
__global__ __launch_bounds__(256) void final_kernel(
    const void* __restrict__ bnodes, float* __restrict__ out)
{
    int warp = (blockIdx.x * 256 + threadIdx.x) >> 5;
    int lane = threadIdx.x & 31;
    if (warp >= N_BATCH) return;
    int node = load_idx(bnodes, warp);
    const float* x = g_x2 + (long)node * OUT;

    float v0 = fmaxf(fmaf(x[lane], g_scale2[lane], g_shift2[lane]), 0.f);
    float v1 = -1e30f;
    if (lane < 8)
        v1 = fmaxf(fmaf(x[32 + lane], g_scale2[32 + lane], g_shift2[32 + lane]), 0.f);

    float m = fmaxf(v0, v1);
    #pragma unroll
    for (int o = 16; o > 0; o >>= 1) m = fmaxf(m, __shfl_xor_sync(0xffffffffu, m, o));
    float e = expf(v0 - m) + (lane < 8 ? expf(v1 - m) : 0.f);
    #pragma unroll
    for (int o = 16; o > 0; o >>= 1) e += __shfl_xor_sync(0xffffffffu, e, o);
    float lz = m + logf(e);

    out[(long)warp * OUT + lane] = v0 - lz;
    if (lane < 8) out[(long)warp * OUT + 32 + lane] = v1 - lz;
}

// ---------------- launcher --------------------------------------------------------
extern "C" void kernel_launch(void* const* d_in, const int* in_sizes, int n_in,
                              void* d_out, int out_size) {
    const float* features = (const float*)d_in[0];
    const void*  edge     = d_in[1];
    const void*  batch    = d_in[2];
    const float* W1 = (const float*)d_in[3];
    const float* b1 = (const float*)d_in[4];
    const float* g1 = (const float*)d_in[5];
    const float* W2 = (const float*)d_in[6];
    const float* b2 = (const float*)d_in[7];
    const float* g2 = (const float*)d_in[8];
    const float* bn1w = (const float*)d_in[9];
    const float* bn1b = (const float*)d_in[10];
    const float* bn2w = (const float*)d_in[11];
    const float* bn2b = (const float*)d_in[12];
    float* out = (float*)d_out;

    // persistent side-stream + fork/join events (created once, outside capture:
    // the harness's first call is the uncaptured correctness run)
    static cudaStream_t s2 = 0;
    static cudaEvent_t ev_fork = 0, ev_join = 0;
    if (!s2) {
        cudaStreamCreateWithFlags(&s2, cudaStreamNonBlocking);
        cudaEventCreateWithFlags(&ev_fork, cudaEventDisableTiming);
        cudaEventCreateWithFlags(&ev_join, cudaEventDisableTiming);
    }

    detect_zero_kernel<<<NB_SCAN, 256>>>(edge);
    cudaEventRecord(ev_fork, 0);

    // ---- side stream: CSR build (independent of the GEMM chain) ----
    cudaStreamWaitEvent(s2, ev_fork, 0);
    hist_kernel<<<(N_EDGES + 255) / 256, 256, 0, s2>>>(edge);
    scan1_kernel<<<NB_SCAN, 256, 0, s2>>>();
    scan2_kernel<<<1, 256, 0, s2>>>();
    scan3_kernel<<<NB_SCAN, 256, 0, s2>>>();
    scatter_kernel<<<(N_EDGES + 255) / 256, 256, 0, s2>>>(edge);
    cudaEventRecord(ev_join, s2);

    // ---- main stream: weight prep + GEMM1 ----
    prepW_kernel<<<(16 * 32 * 32 + 255) / 256, 256>>>(W1);
    prepW2_kernel<<<(16 * 5 * 32 + 255) / 256, 256>>>(W2);
    dim3 gg1((N_NODES + 127) / 128, 2);
    gemm1_tc_kernel<<<gg1, 256>>>(features, b1);

    // join: agg1 needs both gemm1 (main) and CSR (side)
    cudaStreamWaitEvent(0, ev_join, 0);

    agg1_kernel<<<2048, 256>>>(g1);
    bnprep1_kernel<<<1, HID>>>(bn1w, bn1b);

    gemm2_tc_kernel<<<(N_NODES + 511) / 512, 256>>>(b2);
    agg2_kernel<<<1024, 256>>>(g2);
    bnprep2_kernel<<<1, OUT>>>(bn2w, bn2b);

    final_kernel<<<(N_BATCH * 32 + 255) / 256, 256>>>(batch, out);
}